// round 1
// baseline (speedup 1.0000x reference)
#include <cuda_runtime.h>
#include <math.h>

#define NT   2048   // B*T tokens
#define DIM  2048   // model dim
#define HID  1408   // hidden dim
#define NE   16     // experts
#define TOPK 4

// ---- scratch (static device globals; no allocation at runtime) ----
__device__ int   g_counts[NE];
__device__ int   g_entries[NE * NT];        // entry = token*TOPK + k  (slot id)
__device__ float g_slotw[NT * TOPK];        // normalized gate weight per slot
__device__ float g_Hs[(size_t)NT * HID];    // shared-expert hidden
__device__ float g_Hr[(size_t)NT * TOPK * HID]; // routed hidden, indexed by slot

__global__ void zero_counts_kernel() {
    if (threadIdx.x < NE) g_counts[threadIdx.x] = 0;
}

// ---------------- gate: logits -> sigmoid+bias -> top4 -> scatter ----------------
__global__ __launch_bounds__(256) void gate_kernel(const float* __restrict__ x,
                                                   const float* __restrict__ gw,
                                                   const float* __restrict__ gb)
{
    int t = blockIdx.x;
    __shared__ float xs[DIM];
    for (int i = threadIdx.x; i < DIM; i += blockDim.x)
        xs[i] = x[(size_t)t * DIM + i];
    __syncthreads();

    __shared__ float logits[NE];
    int warp = threadIdx.x >> 5, lane = threadIdx.x & 31;
    for (int e = warp; e < NE; e += 8) {
        const float* w = gw + (size_t)e * DIM;
        float s = 0.f;
        for (int d = lane; d < DIM; d += 32) s += w[d] * xs[d];
        #pragma unroll
        for (int o = 16; o > 0; o >>= 1) s += __shfl_down_sync(0xffffffffu, s, o);
        if (lane == 0) logits[e] = s;
    }
    __syncthreads();

    if (threadIdx.x == 0) {
        float sc[NE];
        #pragma unroll
        for (int e = 0; e < NE; e++)
            sc[e] = 1.f / (1.f + expf(-logits[e])) + gb[e];
        int   idx[TOPK];
        float wv[TOPK];
        float sum = 0.f;
        bool used[NE];
        #pragma unroll
        for (int e = 0; e < NE; e++) used[e] = false;
        #pragma unroll
        for (int k = 0; k < TOPK; k++) {
            float best = -1e30f; int bi = 0;
            #pragma unroll
            for (int e = 0; e < NE; e++)
                if (!used[e] && sc[e] > best) { best = sc[e]; bi = e; }
            used[bi] = true; idx[k] = bi; wv[k] = best; sum += best;
        }
        float inv = 1.f / sum;
        #pragma unroll
        for (int k = 0; k < TOPK; k++) {
            int e   = idx[k];
            int pos = atomicAdd(&g_counts[e], 1);
            g_entries[e * NT + pos] = t * TOPK + k;
            g_slotw[t * TOPK + k]   = wv[k] * inv;
        }
    }
}

__device__ __forceinline__ float sigmoidf_(float v) { return 1.f / (1.f + expf(-v)); }

// ---------------- up projection: H = f(x@W1, x@W3) ----------------
// ROUTED: rows gathered via g_entries[e], epilogue silu(h1*h3), store to g_Hr[slot].
// shared: dense rows,                epilogue silu(h1)*h3, store to g_Hs[row].
template<bool ROUTED>
__global__ __launch_bounds__(256) void up_kernel(const float* __restrict__ x,
                                                 const float* __restrict__ W1b,
                                                 const float* __restrict__ W3b,
                                                 float* __restrict__ Hout)
{
    int e  = ROUTED ? blockIdx.z : 0;
    int M  = ROUTED ? g_counts[e] : NT;
    int m0 = blockIdx.x * 64;
    if (m0 >= M) return;
    int n0 = blockIdx.y * 64;
    const float* W1 = W1b + (ROUTED ? (size_t)e * DIM * HID : 0);
    const float* W3 = W3b + (ROUTED ? (size_t)e * DIM * HID : 0);

    __shared__ float As[64][17];
    __shared__ float B1s[16][64];
    __shared__ float B3s[16][64];

    int tid = threadIdx.x;
    int ar = tid >> 2, ak = (tid & 3) << 2;   // A load: row ar, 4 k's
    int bk = tid >> 4, bn = (tid & 15) << 2;  // B load: k row bk, 4 n's
    int ty = tid >> 4, tx = tid & 15;         // compute: rows ty*4.., cols tx*4..

    int arow = m0 + ar;
    const float* aptr = nullptr;
    if (arow < M) {
        int tok = ROUTED ? (g_entries[e * NT + arow] >> 2) : arow;
        aptr = x + (size_t)tok * DIM + ak;
    }

    float c1[4][4] = {}, c3[4][4] = {};

    for (int k0 = 0; k0 < DIM; k0 += 16) {
        float4 av = aptr ? *(const float4*)(aptr + k0) : make_float4(0.f, 0.f, 0.f, 0.f);
        As[ar][ak + 0] = av.x; As[ar][ak + 1] = av.y;
        As[ar][ak + 2] = av.z; As[ar][ak + 3] = av.w;
        *(float4*)&B1s[bk][bn] = *(const float4*)&W1[(size_t)(k0 + bk) * HID + n0 + bn];
        *(float4*)&B3s[bk][bn] = *(const float4*)&W3[(size_t)(k0 + bk) * HID + n0 + bn];
        __syncthreads();
        #pragma unroll
        for (int kk = 0; kk < 16; kk++) {
            float a[4];
            #pragma unroll
            for (int i = 0; i < 4; i++) a[i] = As[ty * 4 + i][kk];
            float4 b1 = *(float4*)&B1s[kk][tx * 4];
            float4 b3 = *(float4*)&B3s[kk][tx * 4];
            float bb1[4] = { b1.x, b1.y, b1.z, b1.w };
            float bb3[4] = { b3.x, b3.y, b3.z, b3.w };
            #pragma unroll
            for (int i = 0; i < 4; i++)
                #pragma unroll
                for (int j = 0; j < 4; j++) {
                    c1[i][j] += a[i] * bb1[j];
                    c3[i][j] += a[i] * bb3[j];
                }
        }
        __syncthreads();
    }

    #pragma unroll
    for (int i = 0; i < 4; i++) {
        int row = m0 + ty * 4 + i;
        if (row >= M) break;
        size_t orow = ROUTED ? (size_t)g_entries[e * NT + row] : (size_t)row;
        float4 o;
        float h[4];
        #pragma unroll
        for (int j = 0; j < 4; j++) {
            if (ROUTED) {
                float p = c1[i][j] * c3[i][j];
                h[j] = p * sigmoidf_(p);              // silu(h1*h2)
            } else {
                h[j] = c1[i][j] * sigmoidf_(c1[i][j]) * c3[i][j]; // silu(h1)*h3
            }
        }
        o.x = h[0]; o.y = h[1]; o.z = h[2]; o.w = h[3];
        *(float4*)&Hout[orow * HID + n0 + tx * 4] = o;
    }
}

// ---------------- down projection: Y = H @ W2 ----------------
// shared: plain store to out. ROUTED: atomicAdd(weight * Y) onto out.
template<bool ROUTED>
__global__ __launch_bounds__(256) void down_kernel(const float* __restrict__ Hin,
                                                   const float* __restrict__ W2b,
                                                   float* __restrict__ out)
{
    int e  = ROUTED ? blockIdx.z : 0;
    int M  = ROUTED ? g_counts[e] : NT;
    int m0 = blockIdx.x * 64;
    if (m0 >= M) return;
    int n0 = blockIdx.y * 64;
    const float* W2 = W2b + (ROUTED ? (size_t)e * HID * DIM : 0);

    __shared__ float As[64][17];
    __shared__ float Bs[16][64];

    int tid = threadIdx.x;
    int ar = tid >> 2, ak = (tid & 3) << 2;
    int bk = tid >> 4, bn = (tid & 15) << 2;
    int ty = tid >> 4, tx = tid & 15;

    int arow = m0 + ar;
    const float* aptr = nullptr;
    if (arow < M) {
        size_t ridx = ROUTED ? (size_t)g_entries[e * NT + arow] : (size_t)arow;
        aptr = Hin + ridx * HID + ak;
    }

    float c[4][4] = {};

    for (int k0 = 0; k0 < HID; k0 += 16) {
        float4 av = aptr ? *(const float4*)(aptr + k0) : make_float4(0.f, 0.f, 0.f, 0.f);
        As[ar][ak + 0] = av.x; As[ar][ak + 1] = av.y;
        As[ar][ak + 2] = av.z; As[ar][ak + 3] = av.w;
        *(float4*)&Bs[bk][bn] = *(const float4*)&W2[(size_t)(k0 + bk) * DIM + n0 + bn];
        __syncthreads();
        #pragma unroll
        for (int kk = 0; kk < 16; kk++) {
            float a[4];
            #pragma unroll
            for (int i = 0; i < 4; i++) a[i] = As[ty * 4 + i][kk];
            float4 b = *(float4*)&Bs[kk][tx * 4];
            float bb[4] = { b.x, b.y, b.z, b.w };
            #pragma unroll
            for (int i = 0; i < 4; i++)
                #pragma unroll
                for (int j = 0; j < 4; j++)
                    c[i][j] += a[i] * bb[j];
        }
        __syncthreads();
    }

    #pragma unroll
    for (int i = 0; i < 4; i++) {
        int row = m0 + ty * 4 + i;
        if (row >= M) break;
        if (ROUTED) {
            int slot = g_entries[e * NT + row];
            int tok  = slot >> 2;
            float w  = g_slotw[slot];
            #pragma unroll
            for (int j = 0; j < 4; j++)
                atomicAdd(&out[(size_t)tok * DIM + n0 + tx * 4 + j], c[i][j] * w);
        } else {
            float4 o;
            o.x = c[0 + 0][0]; // placeholder, replaced below
            o.x = c[i][0]; o.y = c[i][1]; o.z = c[i][2]; o.w = c[i][3];
            *(float4*)&out[(size_t)row * DIM + n0 + tx * 4] = o;
        }
    }
}

extern "C" void kernel_launch(void* const* d_in, const int* in_sizes, int n_in,
                              void* d_out, int out_size)
{
    (void)in_sizes; (void)n_in; (void)out_size;
    const float* x   = (const float*)d_in[0];
    const float* gw  = (const float*)d_in[1];
    const float* gb  = (const float*)d_in[2];
    const float* w1s = (const float*)d_in[3];
    const float* w2s = (const float*)d_in[4];
    const float* w3s = (const float*)d_in[5];
    const float* w1r = (const float*)d_in[6];
    const float* w2r = (const float*)d_in[7];
    const float* w3r = (const float*)d_in[8];
    float* out = (float*)d_out;

    float* Hs; cudaGetSymbolAddress((void**)&Hs, g_Hs);
    float* Hr; cudaGetSymbolAddress((void**)&Hr, g_Hr);

    zero_counts_kernel<<<1, 32>>>();
    gate_kernel<<<NT, 256>>>(x, gw, gb);

    // shared expert
    up_kernel<false><<<dim3(NT / 64, HID / 64), 256>>>(x, w1s, w3s, Hs);
    down_kernel<false><<<dim3(NT / 64, DIM / 64), 256>>>(Hs, w2s, out);

    // routed experts (grouped; blocks past per-expert count exit early)
    up_kernel<true><<<dim3(NT / 64, HID / 64, NE), 256>>>(x, w1r, w3r, Hr);
    down_kernel<true><<<dim3(NT / 64, DIM / 64, NE), 256>>>(Hr, w2r, out);
}

// round 2
// speedup vs baseline: 1.6944x; 1.6944x over previous
#include <cuda_runtime.h>
#include <cuda_bf16.h>
#include <math.h>
#include <stdint.h>

#define NT   2048
#define DIM  2048
#define HID  1408
#define NE   16
#define TOPK 4

// ---- scratch ----
__device__ int   g_counts[NE];
__device__ int   g_entries[NE * NT];            // slot id = token*TOPK + k
__device__ float g_slotw[NT * TOPK];
__device__ float g_Hs[(size_t)NT * HID];
__device__ float g_Hr[(size_t)NT * TOPK * HID];

__global__ void zero_counts_kernel() {
    if (threadIdx.x < NE) g_counts[threadIdx.x] = 0;
}

// ---------------- gate ----------------
__global__ __launch_bounds__(256) void gate_kernel(const float* __restrict__ x,
                                                   const float* __restrict__ gw,
                                                   const float* __restrict__ gb)
{
    int t = blockIdx.x;
    __shared__ float xs[DIM];
    for (int i = threadIdx.x; i < DIM; i += blockDim.x)
        xs[i] = x[(size_t)t * DIM + i];
    __syncthreads();

    __shared__ float logits[NE];
    int warp = threadIdx.x >> 5, lane = threadIdx.x & 31;
    for (int e = warp; e < NE; e += 8) {
        const float* w = gw + (size_t)e * DIM;
        float s = 0.f;
        for (int d = lane; d < DIM; d += 32) s += w[d] * xs[d];
        #pragma unroll
        for (int o = 16; o > 0; o >>= 1) s += __shfl_down_sync(0xffffffffu, s, o);
        if (lane == 0) logits[e] = s;
    }
    __syncthreads();

    if (threadIdx.x == 0) {
        float sc[NE];
        #pragma unroll
        for (int e = 0; e < NE; e++)
            sc[e] = 1.f / (1.f + expf(-logits[e])) + gb[e];
        int idx[TOPK]; float wv[TOPK]; float sum = 0.f;
        bool used[NE];
        #pragma unroll
        for (int e = 0; e < NE; e++) used[e] = false;
        #pragma unroll
        for (int k = 0; k < TOPK; k++) {
            float best = -1e30f; int bi = 0;
            #pragma unroll
            for (int e = 0; e < NE; e++)
                if (!used[e] && sc[e] > best) { best = sc[e]; bi = e; }
            used[bi] = true; idx[k] = bi; wv[k] = best; sum += best;
        }
        float inv = 1.f / sum;
        #pragma unroll
        for (int k = 0; k < TOPK; k++) {
            int e = idx[k];
            int pos = atomicAdd(&g_counts[e], 1);
            g_entries[e * NT + pos] = t * TOPK + k;
            g_slotw[t * TOPK + k]   = wv[k] * inv;
        }
    }
}

__device__ __forceinline__ float sigmoidf_(float v) { return 1.f / (1.f + expf(-v)); }

// ---------------- mma helpers ----------------
__device__ __forceinline__ uint32_t saddr(const void* p) {
    return (uint32_t)__cvta_generic_to_shared(p);
}
__device__ __forceinline__ void ldsm_x4(uint32_t r[4], uint32_t a) {
    asm volatile("ldmatrix.sync.aligned.m8n8.x4.shared.b16 {%0,%1,%2,%3}, [%4];"
                 : "=r"(r[0]), "=r"(r[1]), "=r"(r[2]), "=r"(r[3]) : "r"(a));
}
__device__ __forceinline__ void ldsm_x2t(uint32_t r[2], uint32_t a) {
    asm volatile("ldmatrix.sync.aligned.m8n8.x2.trans.shared.b16 {%0,%1}, [%2];"
                 : "=r"(r[0]), "=r"(r[1]) : "r"(a));
}
__device__ __forceinline__ void mma16816(float c[4], const uint32_t a[4], const uint32_t b[2]) {
    asm volatile("mma.sync.aligned.m16n8k16.row.col.f32.bf16.bf16.f32 "
                 "{%0,%1,%2,%3}, {%4,%5,%6,%7}, {%8,%9}, {%0,%1,%2,%3};"
                 : "+f"(c[0]), "+f"(c[1]), "+f"(c[2]), "+f"(c[3])
                 : "r"(a[0]), "r"(a[1]), "r"(a[2]), "r"(a[3]), "r"(b[0]), "r"(b[1]));
}
__device__ __forceinline__ void split_store(__nv_bfloat16* hi, __nv_bfloat16* lo, float f) {
    __nv_bfloat16 h = __float2bfloat16(f);
    *hi = h;
    *lo = __float2bfloat16(f - __bfloat162float(h));
}

#define APITCH 40
#define BPITCH 72

// ---------------- up: H = f(X@W1, X@W3), 128x64 tiles ----------------
template<bool ROUTED>
__global__ __launch_bounds__(256) void up_mma(const float* __restrict__ x,
                                              const float* __restrict__ W1b,
                                              const float* __restrict__ W3b,
                                              float* __restrict__ Hout)
{
    int e  = ROUTED ? blockIdx.z : 0;
    int M  = ROUTED ? g_counts[e] : NT;
    int m0 = blockIdx.x * 128;
    if (m0 >= M) return;
    int n0 = blockIdx.y * 64;
    const float* W1 = W1b + (ROUTED ? (size_t)e * DIM * HID : 0);
    const float* W3 = W3b + (ROUTED ? (size_t)e * DIM * HID : 0);

    __shared__ __nv_bfloat16 Ah[128][APITCH], Al[128][APITCH];
    __shared__ __nv_bfloat16 Bh[2][32][BPITCH], Bl[2][32][BPITCH];

    int tid = threadIdx.x, lane = tid & 31, warp = tid >> 5;
    int wm = (warp & 3) * 32;
    int wn = (warp >> 2) * 32;

    const float* arow_ptr[4];
    #pragma unroll
    for (int i = 0; i < 4; i++) {
        int idx = tid + i * 256;
        int r = m0 + (idx >> 3);
        if (r < M) {
            int tok = ROUTED ? (g_entries[e * NT + r] >> 2) : r;
            arow_ptr[i] = x + (size_t)tok * DIM + ((idx & 7) << 2);
        } else arow_ptr[i] = nullptr;
    }

    float acc1[2][4][4] = {};
    float acc3[2][4][4] = {};

    for (int k0 = 0; k0 < DIM; k0 += 32) {
        #pragma unroll
        for (int i = 0; i < 4; i++) {
            int idx = tid + i * 256;
            int row = idx >> 3, c = (idx & 7) << 2;
            float4 v = arow_ptr[i] ? *(const float4*)(arow_ptr[i] + k0)
                                   : make_float4(0.f, 0.f, 0.f, 0.f);
            float f[4] = { v.x, v.y, v.z, v.w };
            #pragma unroll
            for (int j = 0; j < 4; j++)
                split_store(&Ah[row][c + j], &Al[row][c + j], f[j]);
        }
        #pragma unroll
        for (int i = 0; i < 2; i++) {
            int idx = tid + i * 256;
            int br = idx >> 4, c = (idx & 15) << 2;
            size_t off = (size_t)(k0 + br) * HID + n0 + c;
            float4 v1 = *(const float4*)(W1 + off);
            float4 v3 = *(const float4*)(W3 + off);
            float f1[4] = { v1.x, v1.y, v1.z, v1.w };
            float f3[4] = { v3.x, v3.y, v3.z, v3.w };
            #pragma unroll
            for (int j = 0; j < 4; j++) {
                split_store(&Bh[0][br][c + j], &Bl[0][br][c + j], f1[j]);
                split_store(&Bh[1][br][c + j], &Bl[1][br][c + j], f3[j]);
            }
        }
        __syncthreads();

        #pragma unroll
        for (int kk = 0; kk < 32; kk += 16) {
            uint32_t ah[2][4], al[2][4];
            #pragma unroll
            for (int mi = 0; mi < 2; mi++) {
                int arow = wm + mi * 16 + (lane & 15);
                int acol = kk + ((lane >> 4) << 3);
                ldsm_x4(ah[mi], saddr(&Ah[arow][acol]));
                ldsm_x4(al[mi], saddr(&Al[arow][acol]));
            }
            #pragma unroll
            for (int ni = 0; ni < 4; ni++) {
                int nn = wn + ni * 8;
                int brow = kk + (lane & 15);
                uint32_t b1h[2], b1l[2], b3h[2], b3l[2];
                ldsm_x2t(b1h, saddr(&Bh[0][brow][nn]));
                ldsm_x2t(b1l, saddr(&Bl[0][brow][nn]));
                ldsm_x2t(b3h, saddr(&Bh[1][brow][nn]));
                ldsm_x2t(b3l, saddr(&Bl[1][brow][nn]));
                #pragma unroll
                for (int mi = 0; mi < 2; mi++) {
                    mma16816(acc1[mi][ni], ah[mi], b1h);
                    mma16816(acc1[mi][ni], ah[mi], b1l);
                    mma16816(acc1[mi][ni], al[mi], b1h);
                    mma16816(acc3[mi][ni], ah[mi], b3h);
                    mma16816(acc3[mi][ni], ah[mi], b3l);
                    mma16816(acc3[mi][ni], al[mi], b3h);
                }
            }
        }
        __syncthreads();
    }

    #pragma unroll
    for (int mi = 0; mi < 2; mi++) {
        #pragma unroll
        for (int half = 0; half < 2; half++) {
            int r = m0 + wm + mi * 16 + (lane >> 2) + half * 8;
            if (r >= M) continue;
            size_t orow = ROUTED ? (size_t)g_entries[e * NT + r] : (size_t)r;
            #pragma unroll
            for (int ni = 0; ni < 4; ni++) {
                float v1a = acc1[mi][ni][half * 2 + 0], v1b = acc1[mi][ni][half * 2 + 1];
                float v3a = acc3[mi][ni][half * 2 + 0], v3b = acc3[mi][ni][half * 2 + 1];
                float2 o;
                if (ROUTED) {
                    float pa = v1a * v3a, pb = v1b * v3b;
                    o.x = pa * sigmoidf_(pa);
                    o.y = pb * sigmoidf_(pb);
                } else {
                    o.x = v1a * sigmoidf_(v1a) * v3a;
                    o.y = v1b * sigmoidf_(v1b) * v3b;
                }
                *(float2*)&Hout[orow * HID + n0 + wn + ni * 8 + ((lane & 3) << 1)] = o;
            }
        }
    }
}

// ---------------- down: Y = H @ W2, 128x64 tiles ----------------
template<bool ROUTED>
__global__ __launch_bounds__(256) void down_mma(const float* __restrict__ Hin,
                                                const float* __restrict__ W2b,
                                                float* __restrict__ out)
{
    int e  = ROUTED ? blockIdx.z : 0;
    int M  = ROUTED ? g_counts[e] : NT;
    int m0 = blockIdx.x * 128;
    if (m0 >= M) return;
    int n0 = blockIdx.y * 64;
    const float* W2 = W2b + (ROUTED ? (size_t)e * HID * DIM : 0);

    __shared__ __nv_bfloat16 Ah[128][APITCH], Al[128][APITCH];
    __shared__ __nv_bfloat16 Bh[32][BPITCH], Bl[32][BPITCH];

    int tid = threadIdx.x, lane = tid & 31, warp = tid >> 5;
    int wm = (warp & 3) * 32;
    int wn = (warp >> 2) * 32;

    const float* arow_ptr[4];
    #pragma unroll
    for (int i = 0; i < 4; i++) {
        int idx = tid + i * 256;
        int r = m0 + (idx >> 3);
        if (r < M) {
            size_t ridx = ROUTED ? (size_t)g_entries[e * NT + r] : (size_t)r;
            arow_ptr[i] = Hin + ridx * HID + ((idx & 7) << 2);
        } else arow_ptr[i] = nullptr;
    }

    float acc[2][4][4] = {};

    for (int k0 = 0; k0 < HID; k0 += 32) {
        #pragma unroll
        for (int i = 0; i < 4; i++) {
            int idx = tid + i * 256;
            int row = idx >> 3, c = (idx & 7) << 2;
            float4 v = arow_ptr[i] ? *(const float4*)(arow_ptr[i] + k0)
                                   : make_float4(0.f, 0.f, 0.f, 0.f);
            float f[4] = { v.x, v.y, v.z, v.w };
            #pragma unroll
            for (int j = 0; j < 4; j++)
                split_store(&Ah[row][c + j], &Al[row][c + j], f[j]);
        }
        #pragma unroll
        for (int i = 0; i < 2; i++) {
            int idx = tid + i * 256;
            int br = idx >> 4, c = (idx & 15) << 2;
            float4 v = *(const float4*)(W2 + (size_t)(k0 + br) * DIM + n0 + c);
            float f[4] = { v.x, v.y, v.z, v.w };
            #pragma unroll
            for (int j = 0; j < 4; j++)
                split_store(&Bh[br][c + j], &Bl[br][c + j], f[j]);
        }
        __syncthreads();

        #pragma unroll
        for (int kk = 0; kk < 32; kk += 16) {
            uint32_t ah[2][4], al[2][4];
            #pragma unroll
            for (int mi = 0; mi < 2; mi++) {
                int arow = wm + mi * 16 + (lane & 15);
                int acol = kk + ((lane >> 4) << 3);
                ldsm_x4(ah[mi], saddr(&Ah[arow][acol]));
                ldsm_x4(al[mi], saddr(&Al[arow][acol]));
            }
            #pragma unroll
            for (int ni = 0; ni < 4; ni++) {
                int nn = wn + ni * 8;
                int brow = kk + (lane & 15);
                uint32_t bh[2], bl[2];
                ldsm_x2t(bh, saddr(&Bh[brow][nn]));
                ldsm_x2t(bl, saddr(&Bl[brow][nn]));
                #pragma unroll
                for (int mi = 0; mi < 2; mi++) {
                    mma16816(acc[mi][ni], ah[mi], bh);
                    mma16816(acc[mi][ni], ah[mi], bl);
                    mma16816(acc[mi][ni], al[mi], bh);
                }
            }
        }
        __syncthreads();
    }

    #pragma unroll
    for (int mi = 0; mi < 2; mi++) {
        #pragma unroll
        for (int half = 0; half < 2; half++) {
            int r = m0 + wm + mi * 16 + (lane >> 2) + half * 8;
            if (r >= M) continue;
            if (ROUTED) {
                int slot = g_entries[e * NT + r];
                int tok  = slot >> 2;
                float w  = g_slotw[slot];
                #pragma unroll
                for (int ni = 0; ni < 4; ni++) {
                    int col = n0 + wn + ni * 8 + ((lane & 3) << 1);
                    atomicAdd(&out[(size_t)tok * DIM + col],     acc[mi][ni][half * 2 + 0] * w);
                    atomicAdd(&out[(size_t)tok * DIM + col + 1], acc[mi][ni][half * 2 + 1] * w);
                }
            } else {
                #pragma unroll
                for (int ni = 0; ni < 4; ni++) {
                    float2 o;
                    o.x = acc[mi][ni][half * 2 + 0];
                    o.y = acc[mi][ni][half * 2 + 1];
                    *(float2*)&out[(size_t)r * DIM + n0 + wn + ni * 8 + ((lane & 3) << 1)] = o;
                }
            }
        }
    }
}

extern "C" void kernel_launch(void* const* d_in, const int* in_sizes, int n_in,
                              void* d_out, int out_size)
{
    (void)in_sizes; (void)n_in; (void)out_size;
    const float* x   = (const float*)d_in[0];
    const float* gw  = (const float*)d_in[1];
    const float* gb  = (const float*)d_in[2];
    const float* w1s = (const float*)d_in[3];
    const float* w2s = (const float*)d_in[4];
    const float* w3s = (const float*)d_in[5];
    const float* w1r = (const float*)d_in[6];
    const float* w2r = (const float*)d_in[7];
    const float* w3r = (const float*)d_in[8];
    float* out = (float*)d_out;

    float* Hs; cudaGetSymbolAddress((void**)&Hs, g_Hs);
    float* Hr; cudaGetSymbolAddress((void**)&Hr, g_Hr);

    zero_counts_kernel<<<1, 32>>>();
    gate_kernel<<<NT, 256>>>(x, gw, gb);

    // shared expert
    up_mma<false><<<dim3(NT / 128, HID / 64), 256>>>(x, w1s, w3s, Hs);
    down_mma<false><<<dim3(NT / 128, DIM / 64), 256>>>(Hs, w2s, out);

    // routed experts
    up_mma<true><<<dim3(NT / 128, HID / 64, NE), 256>>>(x, w1r, w3r, Hr);
    down_mma<true><<<dim3(NT / 128, DIM / 64, NE), 256>>>(Hr, w2r, out);
}

// round 3
// speedup vs baseline: 2.2792x; 1.3451x over previous
#include <cuda_runtime.h>
#include <cuda_bf16.h>
#include <math.h>
#include <stdint.h>

#define NT   2048
#define DIM  2048
#define HID  1408
#define NE   16
#define TOPK 4

typedef __nv_bfloat16 bf16;

// ---- routing scratch ----
__device__ int   g_counts[NE];
__device__ int   g_entries[NE * NT];
__device__ float g_slotw[NT * TOPK];

// ---- bf16 split planes ----
__device__ bf16 g_xh[NT * DIM],  g_xl[NT * DIM];
__device__ bf16 g_w1sh[DIM * HID], g_w1sl[DIM * HID];
__device__ bf16 g_w3sh[DIM * HID], g_w3sl[DIM * HID];
__device__ bf16 g_w2sh[HID * DIM], g_w2sl[HID * DIM];
__device__ bf16 g_w1rh[(size_t)NE * DIM * HID], g_w1rl[(size_t)NE * DIM * HID];
__device__ bf16 g_w3rh[(size_t)NE * DIM * HID], g_w3rl[(size_t)NE * DIM * HID];
__device__ bf16 g_w2rh[(size_t)NE * HID * DIM], g_w2rl[(size_t)NE * HID * DIM];
__device__ bf16 g_Hsh[(size_t)NT * HID], g_Hsl[(size_t)NT * HID];
__device__ bf16 g_Hrh[(size_t)NT * TOPK * HID], g_Hrl[(size_t)NT * TOPK * HID];

__global__ void zero_counts_kernel() {
    if (threadIdx.x < NE) g_counts[threadIdx.x] = 0;
}

// ---------------- fp32 -> bf16 hi/lo split ----------------
__global__ __launch_bounds__(256) void split_kernel(const float* __restrict__ src,
                                                    bf16* __restrict__ hi,
                                                    bf16* __restrict__ lo, int n4)
{
    int i = blockIdx.x * blockDim.x + threadIdx.x;
    if (i >= n4) return;
    float4 v = ((const float4*)src)[i];
    float f[4] = { v.x, v.y, v.z, v.w };
    __align__(8) bf16 h[4];
    __align__(8) bf16 l[4];
    #pragma unroll
    for (int j = 0; j < 4; j++) {
        h[j] = __float2bfloat16(f[j]);
        l[j] = __float2bfloat16(f[j] - __bfloat162float(h[j]));
    }
    *(uint2*)(hi + (size_t)i * 4) = *(uint2*)h;
    *(uint2*)(lo + (size_t)i * 4) = *(uint2*)l;
}

// ---------------- gate ----------------
__global__ __launch_bounds__(256) void gate_kernel(const float* __restrict__ x,
                                                   const float* __restrict__ gw,
                                                   const float* __restrict__ gb)
{
    int t = blockIdx.x;
    __shared__ float xs[DIM];
    for (int i = threadIdx.x; i < DIM; i += blockDim.x)
        xs[i] = x[(size_t)t * DIM + i];
    __syncthreads();

    __shared__ float logits[NE];
    int warp = threadIdx.x >> 5, lane = threadIdx.x & 31;
    for (int e = warp; e < NE; e += 8) {
        const float* w = gw + (size_t)e * DIM;
        float s = 0.f;
        for (int d = lane; d < DIM; d += 32) s += w[d] * xs[d];
        #pragma unroll
        for (int o = 16; o > 0; o >>= 1) s += __shfl_down_sync(0xffffffffu, s, o);
        if (lane == 0) logits[e] = s;
    }
    __syncthreads();

    if (threadIdx.x == 0) {
        float sc[NE];
        #pragma unroll
        for (int e = 0; e < NE; e++)
            sc[e] = 1.f / (1.f + expf(-logits[e])) + gb[e];
        int idx[TOPK]; float wv[TOPK]; float sum = 0.f;
        bool used[NE];
        #pragma unroll
        for (int e = 0; e < NE; e++) used[e] = false;
        #pragma unroll
        for (int k = 0; k < TOPK; k++) {
            float best = -1e30f; int bi = 0;
            #pragma unroll
            for (int e = 0; e < NE; e++)
                if (!used[e] && sc[e] > best) { best = sc[e]; bi = e; }
            used[bi] = true; idx[k] = bi; wv[k] = best; sum += best;
        }
        float inv = 1.f / sum;
        #pragma unroll
        for (int k = 0; k < TOPK; k++) {
            int e = idx[k];
            int pos = atomicAdd(&g_counts[e], 1);
            g_entries[e * NT + pos] = t * TOPK + k;
            g_slotw[t * TOPK + k]   = wv[k] * inv;
        }
    }
}

__device__ __forceinline__ float sigmoidf_(float v) { return 1.f / (1.f + expf(-v)); }

// ---------------- asm helpers ----------------
__device__ __forceinline__ uint32_t saddr(const void* p) {
    return (uint32_t)__cvta_generic_to_shared(p);
}
__device__ __forceinline__ void cpa(uint32_t dst, const void* src) {
    asm volatile("cp.async.cg.shared.global [%0], [%1], 16;" :: "r"(dst), "l"(src));
}
__device__ __forceinline__ void cp_commit() {
    asm volatile("cp.async.commit_group;");
}
__device__ __forceinline__ void cp_wait1() {
    asm volatile("cp.async.wait_group 1;");
}
__device__ __forceinline__ void ldsm_x4(uint32_t r[4], uint32_t a) {
    asm volatile("ldmatrix.sync.aligned.m8n8.x4.shared.b16 {%0,%1,%2,%3}, [%4];"
                 : "=r"(r[0]), "=r"(r[1]), "=r"(r[2]), "=r"(r[3]) : "r"(a));
}
__device__ __forceinline__ void ldsm_x4t(uint32_t r[4], uint32_t a) {
    asm volatile("ldmatrix.sync.aligned.m8n8.x4.trans.shared.b16 {%0,%1,%2,%3}, [%4];"
                 : "=r"(r[0]), "=r"(r[1]), "=r"(r[2]), "=r"(r[3]) : "r"(a));
}
__device__ __forceinline__ void mma16816(float c[4], const uint32_t a[4], const uint32_t b[2]) {
    asm volatile("mma.sync.aligned.m16n8k16.row.col.f32.bf16.bf16.f32 "
                 "{%0,%1,%2,%3}, {%4,%5,%6,%7}, {%8,%9}, {%0,%1,%2,%3};"
                 : "+f"(c[0]), "+f"(c[1]), "+f"(c[2]), "+f"(c[3])
                 : "r"(a[0]), "r"(a[1]), "r"(a[2]), "r"(a[3]), "r"(b[0]), "r"(b[1]));
}
__device__ __forceinline__ void split2(bf16* hp, bf16* lp, float a, float b) {
    __nv_bfloat162 h2, l2;
    h2.x = __float2bfloat16(a); l2.x = __float2bfloat16(a - __bfloat162float(h2.x));
    h2.y = __float2bfloat16(b); l2.y = __float2bfloat16(b - __bfloat162float(h2.y));
    *(__nv_bfloat162*)hp = h2;
    *(__nv_bfloat162*)lp = l2;
}

#define APITCH 40    // bf16; 80B row, 16B-aligned, ldsm conflict-free
#define BPITCH 72    // bf16; 144B row
#define A_ST   (128 * APITCH)   // elems per A plane per stage
#define B_ST   (32 * BPITCH)
#define UP_SMEM   (3 * (2 * A_ST + 4 * B_ST) * 2)
#define DOWN_SMEM (3 * (2 * A_ST + 2 * B_ST) * 2)

// ---------------- up: H = f(X@W1, X@W3) ----------------
template<bool ROUTED>
__global__ __launch_bounds__(256, 1) void up2(
        const bf16* __restrict__ Xh, const bf16* __restrict__ Xl,
        const bf16* __restrict__ W1H, const bf16* __restrict__ W1L,
        const bf16* __restrict__ W3H, const bf16* __restrict__ W3L,
        bf16* __restrict__ Oh, bf16* __restrict__ Ol)
{
    int e  = ROUTED ? blockIdx.z : 0;
    int M  = ROUTED ? g_counts[e] : NT;
    int m0 = blockIdx.x * 128;
    if (m0 >= M) return;
    int n0 = blockIdx.y * 64;
    size_t woff = ROUTED ? (size_t)e * DIM * HID : 0;
    const bf16 *w1h = W1H + woff, *w1l = W1L + woff;
    const bf16 *w3h = W3H + woff, *w3l = W3L + woff;

    extern __shared__ char smem[];
    bf16* sAh  = (bf16*)smem;
    bf16* sAl  = sAh  + 3 * A_ST;
    bf16* sB1h = sAl  + 3 * A_ST;
    bf16* sB1l = sB1h + 3 * B_ST;
    bf16* sB3h = sB1l + 3 * B_ST;
    bf16* sB3l = sB3h + 3 * B_ST;

    int tid = threadIdx.x, lane = tid & 31, warp = tid >> 5;
    int wm = (warp & 3) * 32, wn = (warp >> 2) * 32;

    // A: 2 chunks/thread/plane
    int ar0 = tid >> 2, ac0 = (tid & 3) * 8;
    int ar1 = ar0 + 64;
    int gr0 = m0 + ar0; if (gr0 >= M) gr0 = m0;
    int gr1 = m0 + ar1; if (gr1 >= M) gr1 = m0;
    int tok0 = ROUTED ? (g_entries[e * NT + gr0] >> 2) : gr0;
    int tok1 = ROUTED ? (g_entries[e * NT + gr1] >> 2) : gr1;
    const bf16* srcAh0 = Xh + (size_t)tok0 * DIM + ac0;
    const bf16* srcAl0 = Xl + (size_t)tok0 * DIM + ac0;
    const bf16* srcAh1 = Xh + (size_t)tok1 * DIM + ac0;
    const bf16* srcAl1 = Xl + (size_t)tok1 * DIM + ac0;
    uint32_t dAh0 = saddr(sAh + ar0 * APITCH + ac0);
    uint32_t dAl0 = saddr(sAl + ar0 * APITCH + ac0);
    uint32_t dAh1 = saddr(sAh + ar1 * APITCH + ac0);
    uint32_t dAl1 = saddr(sAl + ar1 * APITCH + ac0);

    // B: 1 chunk/thread/plane
    int br = tid >> 3, bc = (tid & 7) * 8;
    const bf16* s1h = w1h + (size_t)br * HID + n0 + bc;
    const bf16* s1l = w1l + (size_t)br * HID + n0 + bc;
    const bf16* s3h = w3h + (size_t)br * HID + n0 + bc;
    const bf16* s3l = w3l + (size_t)br * HID + n0 + bc;
    uint32_t dB1h = saddr(sB1h + br * BPITCH + bc);
    uint32_t dB1l = saddr(sB1l + br * BPITCH + bc);
    uint32_t dB3h = saddr(sB3h + br * BPITCH + bc);
    uint32_t dB3l = saddr(sB3l + br * BPITCH + bc);

    float acc1[2][4][4] = {}, acc3[2][4][4] = {};

    auto load_stage = [&](int st, int k0) {
        uint32_t ao = st * A_ST * 2;      // bytes
        uint32_t bo = st * B_ST * 2;
        cpa(dAh0 + ao, srcAh0 + k0); cpa(dAl0 + ao, srcAl0 + k0);
        cpa(dAh1 + ao, srcAh1 + k0); cpa(dAl1 + ao, srcAl1 + k0);
        size_t bk = (size_t)k0 * HID;
        cpa(dB1h + bo, s1h + bk); cpa(dB1l + bo, s1l + bk);
        cpa(dB3h + bo, s3h + bk); cpa(dB3l + bo, s3l + bk);
    };

    load_stage(0, 0);  cp_commit();
    load_stage(1, 32); cp_commit();

    const int KT = DIM / 32;
    for (int t = 0; t < KT; t++) {
        cp_wait1();
        __syncthreads();
        int st = t % 3;
        if (t + 2 < KT) load_stage((t + 2) % 3, (t + 2) * 32);
        cp_commit();

        #pragma unroll
        for (int kk = 0; kk < 32; kk += 16) {
            uint32_t ah[2][4], al[2][4];
            #pragma unroll
            for (int mi = 0; mi < 2; mi++) {
                int arow = wm + mi * 16 + (lane & 15);
                int acol = kk + ((lane >> 4) << 3);
                ldsm_x4(ah[mi], saddr(sAh + st * A_ST + arow * APITCH + acol));
                ldsm_x4(al[mi], saddr(sAl + st * A_ST + arow * APITCH + acol));
            }
            uint32_t b1h[2][4], b1l[2][4], b3h[2][4], b3l[2][4];
            #pragma unroll
            for (int g = 0; g < 2; g++) {
                int brw = kk + (lane & 15);
                int bcl = wn + g * 16 + ((lane >> 4) << 3);
                ldsm_x4t(b1h[g], saddr(sB1h + st * B_ST + brw * BPITCH + bcl));
                ldsm_x4t(b1l[g], saddr(sB1l + st * B_ST + brw * BPITCH + bcl));
                ldsm_x4t(b3h[g], saddr(sB3h + st * B_ST + brw * BPITCH + bcl));
                ldsm_x4t(b3l[g], saddr(sB3l + st * B_ST + brw * BPITCH + bcl));
            }
            #pragma unroll
            for (int mi = 0; mi < 2; mi++)
                #pragma unroll
                for (int ni = 0; ni < 4; ni++) {
                    int g = ni >> 1, o = (ni & 1) * 2;
                    mma16816(acc1[mi][ni], ah[mi], &b1h[g][o]);
                    mma16816(acc1[mi][ni], ah[mi], &b1l[g][o]);
                    mma16816(acc1[mi][ni], al[mi], &b1h[g][o]);
                    mma16816(acc3[mi][ni], ah[mi], &b3h[g][o]);
                    mma16816(acc3[mi][ni], ah[mi], &b3l[g][o]);
                    mma16816(acc3[mi][ni], al[mi], &b3h[g][o]);
                }
        }
        __syncthreads();
    }

    #pragma unroll
    for (int mi = 0; mi < 2; mi++)
        #pragma unroll
        for (int half = 0; half < 2; half++) {
            int r = m0 + wm + mi * 16 + (lane >> 2) + half * 8;
            if (r >= M) continue;
            size_t orow = ROUTED ? (size_t)g_entries[e * NT + r] : (size_t)r;
            #pragma unroll
            for (int ni = 0; ni < 4; ni++) {
                float v1a = acc1[mi][ni][half * 2 + 0], v1b = acc1[mi][ni][half * 2 + 1];
                float v3a = acc3[mi][ni][half * 2 + 0], v3b = acc3[mi][ni][half * 2 + 1];
                float oa, ob;
                if (ROUTED) {
                    float pa = v1a * v3a, pb = v1b * v3b;
                    oa = pa * sigmoidf_(pa);
                    ob = pb * sigmoidf_(pb);
                } else {
                    oa = v1a * sigmoidf_(v1a) * v3a;
                    ob = v1b * sigmoidf_(v1b) * v3b;
                }
                size_t off = orow * HID + n0 + wn + ni * 8 + ((lane & 3) << 1);
                split2(Oh + off, Ol + off, oa, ob);
            }
        }
}

// ---------------- down: Y = H @ W2 ----------------
template<bool ROUTED>
__global__ __launch_bounds__(256, 1) void down2(
        const bf16* __restrict__ Hh, const bf16* __restrict__ Hl,
        const bf16* __restrict__ W2H, const bf16* __restrict__ W2L,
        float* __restrict__ out)
{
    int e  = ROUTED ? blockIdx.z : 0;
    int M  = ROUTED ? g_counts[e] : NT;
    int m0 = blockIdx.x * 128;
    if (m0 >= M) return;
    int n0 = blockIdx.y * 64;
    size_t woff = ROUTED ? (size_t)e * HID * DIM : 0;
    const bf16 *w2h = W2H + woff, *w2l = W2L + woff;

    extern __shared__ char smem[];
    bf16* sAh = (bf16*)smem;
    bf16* sAl = sAh + 3 * A_ST;
    bf16* sBh = sAl + 3 * A_ST;
    bf16* sBl = sBh + 3 * B_ST;

    int tid = threadIdx.x, lane = tid & 31, warp = tid >> 5;
    int wm = (warp & 3) * 32, wn = (warp >> 2) * 32;

    int ar0 = tid >> 2, ac0 = (tid & 3) * 8;
    int ar1 = ar0 + 64;
    int gr0 = m0 + ar0; if (gr0 >= M) gr0 = m0;
    int gr1 = m0 + ar1; if (gr1 >= M) gr1 = m0;
    size_t rid0 = ROUTED ? (size_t)g_entries[e * NT + gr0] : (size_t)gr0;
    size_t rid1 = ROUTED ? (size_t)g_entries[e * NT + gr1] : (size_t)gr1;
    const bf16* srcAh0 = Hh + rid0 * HID + ac0;
    const bf16* srcAl0 = Hl + rid0 * HID + ac0;
    const bf16* srcAh1 = Hh + rid1 * HID + ac0;
    const bf16* srcAl1 = Hl + rid1 * HID + ac0;
    uint32_t dAh0 = saddr(sAh + ar0 * APITCH + ac0);
    uint32_t dAl0 = saddr(sAl + ar0 * APITCH + ac0);
    uint32_t dAh1 = saddr(sAh + ar1 * APITCH + ac0);
    uint32_t dAl1 = saddr(sAl + ar1 * APITCH + ac0);

    int br = tid >> 3, bc = (tid & 7) * 8;
    const bf16* sbh = w2h + (size_t)br * DIM + n0 + bc;
    const bf16* sbl = w2l + (size_t)br * DIM + n0 + bc;
    uint32_t dBh = saddr(sBh + br * BPITCH + bc);
    uint32_t dBl = saddr(sBl + br * BPITCH + bc);

    float acc[2][4][4] = {};

    auto load_stage = [&](int st, int k0) {
        uint32_t ao = st * A_ST * 2;
        uint32_t bo = st * B_ST * 2;
        cpa(dAh0 + ao, srcAh0 + k0); cpa(dAl0 + ao, srcAl0 + k0);
        cpa(dAh1 + ao, srcAh1 + k0); cpa(dAl1 + ao, srcAl1 + k0);
        size_t bk = (size_t)k0 * DIM;
        cpa(dBh + bo, sbh + bk); cpa(dBl + bo, sbl + bk);
    };

    load_stage(0, 0);  cp_commit();
    load_stage(1, 32); cp_commit();

    const int KT = HID / 32;
    for (int t = 0; t < KT; t++) {
        cp_wait1();
        __syncthreads();
        int st = t % 3;
        if (t + 2 < KT) load_stage((t + 2) % 3, (t + 2) * 32);
        cp_commit();

        #pragma unroll
        for (int kk = 0; kk < 32; kk += 16) {
            uint32_t ah[2][4], al[2][4];
            #pragma unroll
            for (int mi = 0; mi < 2; mi++) {
                int arow = wm + mi * 16 + (lane & 15);
                int acol = kk + ((lane >> 4) << 3);
                ldsm_x4(ah[mi], saddr(sAh + st * A_ST + arow * APITCH + acol));
                ldsm_x4(al[mi], saddr(sAl + st * A_ST + arow * APITCH + acol));
            }
            uint32_t bh[2][4], bl[2][4];
            #pragma unroll
            for (int g = 0; g < 2; g++) {
                int brw = kk + (lane & 15);
                int bcl = wn + g * 16 + ((lane >> 4) << 3);
                ldsm_x4t(bh[g], saddr(sBh + st * B_ST + brw * BPITCH + bcl));
                ldsm_x4t(bl[g], saddr(sBl + st * B_ST + brw * BPITCH + bcl));
            }
            #pragma unroll
            for (int mi = 0; mi < 2; mi++)
                #pragma unroll
                for (int ni = 0; ni < 4; ni++) {
                    int g = ni >> 1, o = (ni & 1) * 2;
                    mma16816(acc[mi][ni], ah[mi], &bh[g][o]);
                    mma16816(acc[mi][ni], ah[mi], &bl[g][o]);
                    mma16816(acc[mi][ni], al[mi], &bh[g][o]);
                }
        }
        __syncthreads();
    }

    #pragma unroll
    for (int mi = 0; mi < 2; mi++)
        #pragma unroll
        for (int half = 0; half < 2; half++) {
            int r = m0 + wm + mi * 16 + (lane >> 2) + half * 8;
            if (r >= M) continue;
            if (ROUTED) {
                int slot = g_entries[e * NT + r];
                int tok  = slot >> 2;
                float w  = g_slotw[slot];
                #pragma unroll
                for (int ni = 0; ni < 4; ni++) {
                    int col = n0 + wn + ni * 8 + ((lane & 3) << 1);
                    atomicAdd(&out[(size_t)tok * DIM + col],     acc[mi][ni][half * 2 + 0] * w);
                    atomicAdd(&out[(size_t)tok * DIM + col + 1], acc[mi][ni][half * 2 + 1] * w);
                }
            } else {
                #pragma unroll
                for (int ni = 0; ni < 4; ni++) {
                    float2 o;
                    o.x = acc[mi][ni][half * 2 + 0];
                    o.y = acc[mi][ni][half * 2 + 1];
                    *(float2*)&out[(size_t)r * DIM + n0 + wn + ni * 8 + ((lane & 3) << 1)] = o;
                }
            }
        }
}

static void* sym(const void* s) { void* p; cudaGetSymbolAddress(&p, s); return p; }

extern "C" void kernel_launch(void* const* d_in, const int* in_sizes, int n_in,
                              void* d_out, int out_size)
{
    (void)in_sizes; (void)n_in; (void)out_size;
    const float* x   = (const float*)d_in[0];
    const float* gw  = (const float*)d_in[1];
    const float* gb  = (const float*)d_in[2];
    const float* w1s = (const float*)d_in[3];
    const float* w2s = (const float*)d_in[4];
    const float* w3s = (const float*)d_in[5];
    const float* w1r = (const float*)d_in[6];
    const float* w2r = (const float*)d_in[7];
    const float* w3r = (const float*)d_in[8];
    float* out = (float*)d_out;

    bf16 *xh = (bf16*)sym(g_xh), *xl = (bf16*)sym(g_xl);
    bf16 *w1sh = (bf16*)sym(g_w1sh), *w1sl = (bf16*)sym(g_w1sl);
    bf16 *w3sh = (bf16*)sym(g_w3sh), *w3sl = (bf16*)sym(g_w3sl);
    bf16 *w2sh = (bf16*)sym(g_w2sh), *w2sl = (bf16*)sym(g_w2sl);
    bf16 *w1rh = (bf16*)sym(g_w1rh), *w1rl = (bf16*)sym(g_w1rl);
    bf16 *w3rh = (bf16*)sym(g_w3rh), *w3rl = (bf16*)sym(g_w3rl);
    bf16 *w2rh = (bf16*)sym(g_w2rh), *w2rl = (bf16*)sym(g_w2rl);
    bf16 *Hsh = (bf16*)sym(g_Hsh), *Hsl = (bf16*)sym(g_Hsl);
    bf16 *Hrh = (bf16*)sym(g_Hrh), *Hrl = (bf16*)sym(g_Hrl);

    static bool attr_done = false;
    cudaFuncSetAttribute(up2<false>,  cudaFuncAttributeMaxDynamicSharedMemorySize, UP_SMEM);
    cudaFuncSetAttribute(up2<true>,   cudaFuncAttributeMaxDynamicSharedMemorySize, UP_SMEM);
    cudaFuncSetAttribute(down2<false>, cudaFuncAttributeMaxDynamicSharedMemorySize, DOWN_SMEM);
    cudaFuncSetAttribute(down2<true>,  cudaFuncAttributeMaxDynamicSharedMemorySize, DOWN_SMEM);
    (void)attr_done;

    auto split = [&](const float* s, bf16* h, bf16* l, size_t n) {
        int n4 = (int)(n / 4);
        split_kernel<<<(n4 + 255) / 256, 256>>>(s, h, l, n4);
    };

    zero_counts_kernel<<<1, 32>>>();
    gate_kernel<<<NT, 256>>>(x, gw, gb);

    split(x,   xh,   xl,   (size_t)NT * DIM);
    split(w1s, w1sh, w1sl, (size_t)DIM * HID);
    split(w3s, w3sh, w3sl, (size_t)DIM * HID);
    split(w2s, w2sh, w2sl, (size_t)HID * DIM);
    split(w1r, w1rh, w1rl, (size_t)NE * DIM * HID);
    split(w3r, w3rh, w3rl, (size_t)NE * DIM * HID);
    split(w2r, w2rh, w2rl, (size_t)NE * HID * DIM);

    // shared expert
    up2<false><<<dim3(NT / 128, HID / 64), 256, UP_SMEM>>>(xh, xl, w1sh, w1sl, w3sh, w3sl, Hsh, Hsl);
    down2<false><<<dim3(NT / 128, DIM / 64), 256, DOWN_SMEM>>>(Hsh, Hsl, w2sh, w2sl, out);

    // routed experts
    up2<true><<<dim3(NT / 128, HID / 64, NE), 256, UP_SMEM>>>(xh, xl, w1rh, w1rl, w3rh, w3rl, Hrh, Hrl);
    down2<true><<<dim3(NT / 128, DIM / 64, NE), 256, DOWN_SMEM>>>(Hrh, Hrl, w2rh, w2rl, out);
}

// round 5
// speedup vs baseline: 2.9652x; 1.3010x over previous
#include <cuda_runtime.h>
#include <cuda_fp16.h>
#include <math.h>
#include <stdint.h>

#define NT   2048
#define DIM  2048
#define HID  1408
#define NE   16
#define TOPK 4
#define KC   32

typedef __half fp16;

// ---- routing scratch ----
__device__ int   g_counts[NE];
__device__ int   g_entries[NE * NT];
__device__ float g_slotw[NT * TOPK];

// ---- fp16 planes: activations split (hi+lo), weights single plane ----
__device__ fp16 g_xh[NT * DIM], g_xl[NT * DIM];
__device__ fp16 g_w1s[DIM * HID], g_w3s[DIM * HID], g_w2s[HID * DIM];
__device__ fp16 g_w1r[(size_t)NE * DIM * HID];
__device__ fp16 g_w3r[(size_t)NE * DIM * HID];
__device__ fp16 g_w2r[(size_t)NE * HID * DIM];
__device__ fp16 g_Hsh[(size_t)NT * HID], g_Hsl[(size_t)NT * HID];
__device__ fp16 g_Hrh[(size_t)NT * TOPK * HID], g_Hrl[(size_t)NT * TOPK * HID];

__global__ void zero_counts_kernel() {
    if (threadIdx.x < NE) g_counts[threadIdx.x] = 0;
}

// ---------------- fp32 -> fp16 hi/lo split (activations) ----------------
__global__ __launch_bounds__(256) void split_kernel(const float* __restrict__ src,
                                                    fp16* __restrict__ hi,
                                                    fp16* __restrict__ lo, int n4)
{
    int i = blockIdx.x * blockDim.x + threadIdx.x;
    if (i >= n4) return;
    float4 v = ((const float4*)src)[i];
    float f[4] = { v.x, v.y, v.z, v.w };
    __align__(8) fp16 h[4];
    __align__(8) fp16 l[4];
    #pragma unroll
    for (int j = 0; j < 4; j++) {
        h[j] = __float2half_rn(f[j]);
        l[j] = __float2half_rn(f[j] - __half2float(h[j]));
    }
    __stcs((uint2*)(hi + (size_t)i * 4), *(uint2*)h);
    __stcs((uint2*)(lo + (size_t)i * 4), *(uint2*)l);
}

// ---------------- fp32 -> fp16 single-plane convert (weights) ----------------
__global__ __launch_bounds__(256) void cvt_kernel(const float* __restrict__ src,
                                                  fp16* __restrict__ dst, int n4)
{
    int i = blockIdx.x * blockDim.x + threadIdx.x;
    if (i >= n4) return;
    float4 v = ((const float4*)src)[i];
    __align__(8) fp16 h[4];
    h[0] = __float2half_rn(v.x); h[1] = __float2half_rn(v.y);
    h[2] = __float2half_rn(v.z); h[3] = __float2half_rn(v.w);
    __stcs((uint2*)(dst + (size_t)i * 4), *(uint2*)h);
}

// ---------------- gate ----------------
__global__ __launch_bounds__(256) void gate_kernel(const float* __restrict__ x,
                                                   const float* __restrict__ gw,
                                                   const float* __restrict__ gb)
{
    int t = blockIdx.x;
    __shared__ float xs[DIM];
    for (int i = threadIdx.x; i < DIM; i += blockDim.x)
        xs[i] = x[(size_t)t * DIM + i];
    __syncthreads();

    __shared__ float logits[NE];
    int warp = threadIdx.x >> 5, lane = threadIdx.x & 31;
    for (int e = warp; e < NE; e += 8) {
        const float* w = gw + (size_t)e * DIM;
        float s = 0.f;
        for (int d = lane; d < DIM; d += 32) s += w[d] * xs[d];
        #pragma unroll
        for (int o = 16; o > 0; o >>= 1) s += __shfl_down_sync(0xffffffffu, s, o);
        if (lane == 0) logits[e] = s;
    }
    __syncthreads();

    if (threadIdx.x == 0) {
        float sc[NE];
        #pragma unroll
        for (int e = 0; e < NE; e++)
            sc[e] = 1.f / (1.f + expf(-logits[e])) + gb[e];
        int idx[TOPK]; float wv[TOPK]; float sum = 0.f;
        bool used[NE];
        #pragma unroll
        for (int e = 0; e < NE; e++) used[e] = false;
        #pragma unroll
        for (int k = 0; k < TOPK; k++) {
            float best = -1e30f; int bi = 0;
            #pragma unroll
            for (int e = 0; e < NE; e++)
                if (!used[e] && sc[e] > best) { best = sc[e]; bi = e; }
            used[bi] = true; idx[k] = bi; wv[k] = best; sum += best;
        }
        float inv = 1.f / sum;
        #pragma unroll
        for (int k = 0; k < TOPK; k++) {
            int e = idx[k];
            int pos = atomicAdd(&g_counts[e], 1);
            g_entries[e * NT + pos] = t * TOPK + k;
            g_slotw[t * TOPK + k]   = wv[k] * inv;
        }
    }
}

__device__ __forceinline__ float sigmoidf_(float v) { return 1.f / (1.f + expf(-v)); }

// ---------------- asm helpers ----------------
__device__ __forceinline__ uint32_t saddr(const void* p) {
    return (uint32_t)__cvta_generic_to_shared(p);
}
__device__ __forceinline__ void cpa(uint32_t dst, const void* src) {
    asm volatile("cp.async.cg.shared.global [%0], [%1], 16;" :: "r"(dst), "l"(src));
}
__device__ __forceinline__ void cp_commit() { asm volatile("cp.async.commit_group;"); }
__device__ __forceinline__ void cp_wait2()  { asm volatile("cp.async.wait_group 2;"); }
__device__ __forceinline__ void ldsm_x4(uint32_t r[4], uint32_t a) {
    asm volatile("ldmatrix.sync.aligned.m8n8.x4.shared.b16 {%0,%1,%2,%3}, [%4];"
                 : "=r"(r[0]), "=r"(r[1]), "=r"(r[2]), "=r"(r[3]) : "r"(a));
}
__device__ __forceinline__ void ldsm_x4t(uint32_t r[4], uint32_t a) {
    asm volatile("ldmatrix.sync.aligned.m8n8.x4.trans.shared.b16 {%0,%1,%2,%3}, [%4];"
                 : "=r"(r[0]), "=r"(r[1]), "=r"(r[2]), "=r"(r[3]) : "r"(a));
}
__device__ __forceinline__ void mma16816(float c[4], const uint32_t a[4], const uint32_t b[2]) {
    asm volatile("mma.sync.aligned.m16n8k16.row.col.f32.f16.f16.f32 "
                 "{%0,%1,%2,%3}, {%4,%5,%6,%7}, {%8,%9}, {%0,%1,%2,%3};"
                 : "+f"(c[0]), "+f"(c[1]), "+f"(c[2]), "+f"(c[3])
                 : "r"(a[0]), "r"(a[1]), "r"(a[2]), "r"(a[3]), "r"(b[0]), "r"(b[1]));
}
__device__ __forceinline__ void split2h(fp16* hp, fp16* lp, float a, float b) {
    __half2 h2, l2;
    h2.x = __float2half_rn(a); l2.x = __float2half_rn(a - __half2float(h2.x));
    h2.y = __float2half_rn(b); l2.y = __float2half_rn(b - __half2float(h2.y));
    *(__half2*)hp = h2;
    *(__half2*)lp = l2;
}

#define APITCH 40     // fp16 elems; 80B rows: conflict-free for ldsm
#define BP_UP  72     // 144B rows
#define BP_DN  136    // 272B rows
#define A_ST   (128 * APITCH)
#define BU_ST  (32 * BP_UP)
#define BD_ST  (32 * BP_DN)
#define UP_STAGE   ((2 * A_ST + 2 * BU_ST) * 2)   // bytes
#define DOWN_STAGE ((2 * A_ST + BD_ST) * 2)
#define UP_SMEM    (4 * UP_STAGE)
#define DOWN_SMEM  (4 * DOWN_STAGE)

// ================ up: H = f(X@W1, X@W3), tile 128(M) x 64(H cols) ================
template<bool ROUTED>
__global__ __launch_bounds__(256, 1) void up_k(
        const fp16* __restrict__ Xh, const fp16* __restrict__ Xl,
        const fp16* __restrict__ W1, const fp16* __restrict__ W3,
        fp16* __restrict__ Oh, fp16* __restrict__ Ol)
{
    int e  = ROUTED ? blockIdx.z : 0;
    int M  = ROUTED ? g_counts[e] : NT;
    int m0 = blockIdx.x * 128;
    if (m0 >= M) return;
    int n0 = blockIdx.y * 64;
    size_t woff = ROUTED ? (size_t)e * DIM * HID : 0;
    const fp16* w1 = W1 + woff;
    const fp16* w3 = W3 + woff;

    extern __shared__ char smem[];
    fp16* sAh = (fp16*)smem;                 // 4 stages contiguous per plane? no: per-stage blocks
    // layout per stage: [Ah | Al | B1 | B3]
    int tid = threadIdx.x, lane = tid & 31, warp = tid >> 5;
    int wm = (warp & 3) * 32, wn = (warp >> 2) * 32;

    int ar = tid >> 1, ac = (tid & 1) * 16;
    int gr = m0 + ar; if (gr >= M) gr = m0;
    int tok = ROUTED ? (g_entries[e * NT + gr] >> 2) : gr;
    const fp16* srcAh = Xh + (size_t)tok * DIM + ac;
    const fp16* srcAl = Xl + (size_t)tok * DIM + ac;

    int br = tid >> 3, bc = (tid & 7) * 8;
    const fp16* src1 = w1 + (size_t)br * HID + n0 + bc;
    const fp16* src3 = w3 + (size_t)br * HID + n0 + bc;

    uint32_t sb = saddr(smem);
    uint32_t offAh = (uint32_t)(ar * APITCH + ac) * 2;
    uint32_t offAl = offAh + A_ST * 2;
    uint32_t offB1 = (2 * A_ST + br * BP_UP + bc) * 2;
    uint32_t offB3 = offB1 + BU_ST * 2;

    float acc1[2][4][4] = {}, acc3[2][4][4] = {};

    auto load_stage = [&](int st, int k0) {
        uint32_t base = sb + st * UP_STAGE;
        cpa(base + offAh,      srcAh + k0);
        cpa(base + offAh + 16, srcAh + k0 + 8);
        cpa(base + offAl,      srcAl + k0);
        cpa(base + offAl + 16, srcAl + k0 + 8);
        size_t rk = (size_t)k0 * HID;
        cpa(base + offB1, src1 + rk);
        cpa(base + offB3, src3 + rk);
    };

    load_stage(0, 0);      cp_commit();
    load_stage(1, KC);     cp_commit();
    load_stage(2, 2 * KC); cp_commit();

    const int KT = DIM / KC;
    for (int t = 0; t < KT; t++) {
        int st = t & 3;
        cp_wait2();
        __syncthreads();
        if (t + 3 < KT) load_stage((t + 3) & 3, (t + 3) * KC);
        cp_commit();

        uint32_t base = sb + st * UP_STAGE;
        #pragma unroll
        for (int kk = 0; kk < KC; kk += 16) {
            uint32_t ah[2][4], al[2][4];
            #pragma unroll
            for (int mi = 0; mi < 2; mi++) {
                uint32_t ao = ((wm + mi * 16 + (lane & 15)) * APITCH + kk + ((lane >> 4) << 3)) * 2;
                ldsm_x4(ah[mi], base + ao);
                ldsm_x4(al[mi], base + A_ST * 2 + ao);
            }
            uint32_t b1[2][4], b3[2][4];
            #pragma unroll
            for (int g = 0; g < 2; g++) {
                uint32_t bo = ((kk + (lane & 15)) * BP_UP + wn + g * 16 + ((lane >> 4) << 3)) * 2;
                ldsm_x4t(b1[g], base + (2 * A_ST) * 2 + bo);
                ldsm_x4t(b3[g], base + (2 * A_ST + BU_ST) * 2 + bo);
            }
            #pragma unroll
            for (int ni = 0; ni < 4; ni++) {
                int g = ni >> 1, o = (ni & 1) * 2;
                #pragma unroll
                for (int mi = 0; mi < 2; mi++) {
                    mma16816(acc1[mi][ni], ah[mi], &b1[g][o]);
                    mma16816(acc1[mi][ni], al[mi], &b1[g][o]);
                    mma16816(acc3[mi][ni], ah[mi], &b3[g][o]);
                    mma16816(acc3[mi][ni], al[mi], &b3[g][o]);
                }
            }
        }
        __syncthreads();
    }

    #pragma unroll
    for (int mi = 0; mi < 2; mi++)
        #pragma unroll
        for (int half = 0; half < 2; half++) {
            int r = m0 + wm + mi * 16 + (lane >> 2) + half * 8;
            if (r >= M) continue;
            size_t orow = ROUTED ? (size_t)g_entries[e * NT + r] : (size_t)r;
            #pragma unroll
            for (int ni = 0; ni < 4; ni++) {
                float v1a = acc1[mi][ni][half * 2 + 0], v1b = acc1[mi][ni][half * 2 + 1];
                float v3a = acc3[mi][ni][half * 2 + 0], v3b = acc3[mi][ni][half * 2 + 1];
                float oa, ob;
                if (ROUTED) {
                    float pa = v1a * v3a, pb = v1b * v3b;
                    oa = pa * sigmoidf_(pa);
                    ob = pb * sigmoidf_(pb);
                } else {
                    oa = v1a * sigmoidf_(v1a) * v3a;
                    ob = v1b * sigmoidf_(v1b) * v3b;
                }
                size_t off = orow * HID + n0 + wn + ni * 8 + ((lane & 3) << 1);
                split2h(Oh + off, Ol + off, oa, ob);
            }
        }
}

// ================ down: Y = H @ W2, tile 128(M) x 128(N) ================
template<bool ROUTED>
__global__ __launch_bounds__(256, 1) void down_k(
        const fp16* __restrict__ Hh, const fp16* __restrict__ Hl,
        const fp16* __restrict__ W2, float* __restrict__ out)
{
    int e  = ROUTED ? blockIdx.z : 0;
    int M  = ROUTED ? g_counts[e] : NT;
    int m0 = blockIdx.x * 128;
    if (m0 >= M) return;
    int n0 = blockIdx.y * 128;
    size_t woff = ROUTED ? (size_t)e * HID * DIM : 0;
    const fp16* w2 = W2 + woff;

    extern __shared__ char smem[];
    int tid = threadIdx.x, lane = tid & 31, warp = tid >> 5;
    int wm = (warp & 1) * 64, wn = (warp >> 1) * 32;

    int ar = tid >> 1, ac = (tid & 1) * 16;
    int gr = m0 + ar; if (gr >= M) gr = m0;
    size_t rid = ROUTED ? (size_t)g_entries[e * NT + gr] : (size_t)gr;
    const fp16* srcAh = Hh + rid * HID + ac;
    const fp16* srcAl = Hl + rid * HID + ac;

    int br = tid >> 3, bc = (tid & 7) * 16;
    const fp16* srcB = w2 + (size_t)br * DIM + n0 + bc;

    uint32_t sb = saddr(smem);
    uint32_t offAh = (uint32_t)(ar * APITCH + ac) * 2;
    uint32_t offAl = offAh + A_ST * 2;
    uint32_t offB  = (2 * A_ST + br * BP_DN + bc) * 2;

    float acc[4][4][4] = {};

    auto load_stage = [&](int st, int k0) {
        uint32_t base = sb + st * DOWN_STAGE;
        cpa(base + offAh,      srcAh + k0);
        cpa(base + offAh + 16, srcAh + k0 + 8);
        cpa(base + offAl,      srcAl + k0);
        cpa(base + offAl + 16, srcAl + k0 + 8);
        size_t rk = (size_t)k0 * DIM;
        cpa(base + offB,      srcB + rk);
        cpa(base + offB + 16, srcB + rk + 8);
    };

    load_stage(0, 0);      cp_commit();
    load_stage(1, KC);     cp_commit();
    load_stage(2, 2 * KC); cp_commit();

    const int KT = HID / KC;
    for (int t = 0; t < KT; t++) {
        int st = t & 3;
        cp_wait2();
        __syncthreads();
        if (t + 3 < KT) load_stage((t + 3) & 3, (t + 3) * KC);
        cp_commit();

        uint32_t base = sb + st * DOWN_STAGE;
        #pragma unroll
        for (int kk = 0; kk < KC; kk += 16) {
            uint32_t ah[4][4], al[4][4];
            #pragma unroll
            for (int mi = 0; mi < 4; mi++) {
                uint32_t ao = ((wm + mi * 16 + (lane & 15)) * APITCH + kk + ((lane >> 4) << 3)) * 2;
                ldsm_x4(ah[mi], base + ao);
                ldsm_x4(al[mi], base + A_ST * 2 + ao);
            }
            uint32_t bh[2][4];
            #pragma unroll
            for (int g = 0; g < 2; g++) {
                uint32_t bo = ((kk + (lane & 15)) * BP_DN + wn + g * 16 + ((lane >> 4) << 3)) * 2;
                ldsm_x4t(bh[g], base + (2 * A_ST) * 2 + bo);
            }
            #pragma unroll
            for (int ni = 0; ni < 4; ni++) {
                int g = ni >> 1, o = (ni & 1) * 2;
                #pragma unroll
                for (int mi = 0; mi < 4; mi++) {
                    mma16816(acc[mi][ni], ah[mi], &bh[g][o]);
                    mma16816(acc[mi][ni], al[mi], &bh[g][o]);
                }
            }
        }
        __syncthreads();
    }

    #pragma unroll
    for (int mi = 0; mi < 4; mi++)
        #pragma unroll
        for (int half = 0; half < 2; half++) {
            int r = m0 + wm + mi * 16 + (lane >> 2) + half * 8;
            if (r >= M) continue;
            if (ROUTED) {
                int slot = g_entries[e * NT + r];
                int tok  = slot >> 2;
                float w  = g_slotw[slot];
                #pragma unroll
                for (int ni = 0; ni < 4; ni++) {
                    int col = n0 + wn + ni * 8 + ((lane & 3) << 1);
                    atomicAdd(&out[(size_t)tok * DIM + col],     acc[mi][ni][half * 2 + 0] * w);
                    atomicAdd(&out[(size_t)tok * DIM + col + 1], acc[mi][ni][half * 2 + 1] * w);
                }
            } else {
                #pragma unroll
                for (int ni = 0; ni < 4; ni++) {
                    float2 o;
                    o.x = acc[mi][ni][half * 2 + 0];
                    o.y = acc[mi][ni][half * 2 + 1];
                    *(float2*)&out[(size_t)r * DIM + n0 + wn + ni * 8 + ((lane & 3) << 1)] = o;
                }
            }
        }
}

static void* sym(const void* s) { void* p; cudaGetSymbolAddress(&p, s); return p; }

extern "C" void kernel_launch(void* const* d_in, const int* in_sizes, int n_in,
                              void* d_out, int out_size)
{
    (void)in_sizes; (void)n_in; (void)out_size;
    const float* x   = (const float*)d_in[0];
    const float* gw  = (const float*)d_in[1];
    const float* gb  = (const float*)d_in[2];
    const float* w1s = (const float*)d_in[3];
    const float* w2s = (const float*)d_in[4];
    const float* w3s = (const float*)d_in[5];
    const float* w1r = (const float*)d_in[6];
    const float* w2r = (const float*)d_in[7];
    const float* w3r = (const float*)d_in[8];
    float* out = (float*)d_out;

    fp16 *xh = (fp16*)sym(g_xh), *xl = (fp16*)sym(g_xl);
    fp16 *pw1s = (fp16*)sym(g_w1s), *pw3s = (fp16*)sym(g_w3s), *pw2s = (fp16*)sym(g_w2s);
    fp16 *pw1r = (fp16*)sym(g_w1r), *pw3r = (fp16*)sym(g_w3r), *pw2r = (fp16*)sym(g_w2r);
    fp16 *Hsh = (fp16*)sym(g_Hsh), *Hsl = (fp16*)sym(g_Hsl);
    fp16 *Hrh = (fp16*)sym(g_Hrh), *Hrl = (fp16*)sym(g_Hrl);

    cudaFuncSetAttribute(up_k<false>,  cudaFuncAttributeMaxDynamicSharedMemorySize, UP_SMEM);
    cudaFuncSetAttribute(up_k<true>,   cudaFuncAttributeMaxDynamicSharedMemorySize, UP_SMEM);
    cudaFuncSetAttribute(down_k<false>, cudaFuncAttributeMaxDynamicSharedMemorySize, DOWN_SMEM);
    cudaFuncSetAttribute(down_k<true>,  cudaFuncAttributeMaxDynamicSharedMemorySize, DOWN_SMEM);

    auto cvt = [&](const float* s, fp16* d, size_t n) {
        int n4 = (int)(n / 4);
        cvt_kernel<<<(n4 + 255) / 256, 256>>>(s, d, n4);
    };

    zero_counts_kernel<<<1, 32>>>();
    gate_kernel<<<NT, 256>>>(x, gw, gb);

    {
        int n4 = (int)((size_t)NT * DIM / 4);
        split_kernel<<<(n4 + 255) / 256, 256>>>(x, xh, xl, n4);
    }
    cvt(w1s, pw1s, (size_t)DIM * HID);
    cvt(w3s, pw3s, (size_t)DIM * HID);
    cvt(w2s, pw2s, (size_t)HID * DIM);
    cvt(w1r, pw1r, (size_t)NE * DIM * HID);
    cvt(w3r, pw3r, (size_t)NE * DIM * HID);
    cvt(w2r, pw2r, (size_t)NE * HID * DIM);

    // shared expert
    up_k<false><<<dim3(NT / 128, HID / 64), 256, UP_SMEM>>>(xh, xl, pw1s, pw3s, Hsh, Hsl);
    down_k<false><<<dim3(NT / 128, DIM / 128), 256, DOWN_SMEM>>>(Hsh, Hsl, pw2s, out);

    // routed experts
    up_k<true><<<dim3(NT / 128, HID / 64, NE), 256, UP_SMEM>>>(xh, xl, pw1r, pw3r, Hrh, Hrl);
    down_k<true><<<dim3(NT / 128, DIM / 128, NE), 256, DOWN_SMEM>>>(Hrh, Hrl, pw2r, out);
}

// round 6
// speedup vs baseline: 3.3886x; 1.1428x over previous
#include <cuda_runtime.h>
#include <cuda_fp16.h>
#include <math.h>
#include <stdint.h>

#define NT   2048
#define DIM  2048
#define HID  1408
#define NE   16
#define TOPK 4
#define KC   32

typedef __half fp16;

// ---- routing scratch ----
__device__ int   g_counts[NE];
__device__ int   g_entries[NE * NT];
__device__ float g_slotw[NT * TOPK];

// ---- fp16 planes ----
__device__ fp16 g_xh[NT * DIM], g_xl[NT * DIM];
__device__ fp16 g_w1s[DIM * HID], g_w3s[DIM * HID], g_w2s[HID * DIM];
__device__ fp16 g_w1r[(size_t)NE * DIM * HID];
__device__ fp16 g_w3r[(size_t)NE * DIM * HID];
__device__ fp16 g_w2r[(size_t)NE * HID * DIM];
__device__ fp16 g_Hs[(size_t)NT * HID];
__device__ fp16 g_Hr[(size_t)NT * TOPK * HID];

__global__ void zero_counts_kernel() {
    if (threadIdx.x < NE) g_counts[threadIdx.x] = 0;
}

// ---------------- fp32 -> fp16 hi/lo split (x only), MLP-4 ----------------
__global__ __launch_bounds__(256) void split_kernel(const float* __restrict__ src,
                                                    fp16* __restrict__ hi,
                                                    fp16* __restrict__ lo, int n4)
{
    int stride = gridDim.x * blockDim.x;
    for (int i = blockIdx.x * blockDim.x + threadIdx.x; i < n4; i += stride) {
        float4 v = __ldcs(((const float4*)src) + i);
        float f[4] = { v.x, v.y, v.z, v.w };
        __align__(8) fp16 h[4];
        __align__(8) fp16 l[4];
        #pragma unroll
        for (int j = 0; j < 4; j++) {
            h[j] = __float2half_rn(f[j]);
            l[j] = __float2half_rn(f[j] - __half2float(h[j]));
        }
        __stcs((uint2*)(hi + (size_t)i * 4), *(uint2*)h);
        __stcs((uint2*)(lo + (size_t)i * 4), *(uint2*)l);
    }
}

// ---------------- fp32 -> fp16 convert (weights), MLP-4 ----------------
__global__ __launch_bounds__(256) void cvt_kernel(const float* __restrict__ src,
                                                  fp16* __restrict__ dst, int n4)
{
    int base = (blockIdx.x * blockDim.x + threadIdx.x) * 4;
    int stride = gridDim.x * blockDim.x * 4;
    for (int i0 = base; i0 < n4; i0 += stride) {
        float4 v[4];
        int cnt = min(4, n4 - i0);
        #pragma unroll
        for (int j = 0; j < 4; j++)
            if (j < cnt) v[j] = __ldcs(((const float4*)src) + i0 + j);
        #pragma unroll
        for (int j = 0; j < 4; j++) {
            if (j >= cnt) break;
            __align__(8) fp16 h[4];
            h[0] = __float2half_rn(v[j].x); h[1] = __float2half_rn(v[j].y);
            h[2] = __float2half_rn(v[j].z); h[3] = __float2half_rn(v[j].w);
            __stcs((uint2*)(dst + (size_t)(i0 + j) * 4), *(uint2*)h);
        }
    }
}

// ---------------- gate ----------------
__global__ __launch_bounds__(256) void gate_kernel(const float* __restrict__ x,
                                                   const float* __restrict__ gw,
                                                   const float* __restrict__ gb)
{
    int t = blockIdx.x;
    __shared__ float xs[DIM];
    for (int i = threadIdx.x; i < DIM; i += blockDim.x)
        xs[i] = x[(size_t)t * DIM + i];
    __syncthreads();

    __shared__ float logits[NE];
    int warp = threadIdx.x >> 5, lane = threadIdx.x & 31;
    for (int e = warp; e < NE; e += 8) {
        const float* w = gw + (size_t)e * DIM;
        float s = 0.f;
        for (int d = lane; d < DIM; d += 32) s += w[d] * xs[d];
        #pragma unroll
        for (int o = 16; o > 0; o >>= 1) s += __shfl_down_sync(0xffffffffu, s, o);
        if (lane == 0) logits[e] = s;
    }
    __syncthreads();

    if (threadIdx.x == 0) {
        float sc[NE];
        #pragma unroll
        for (int e = 0; e < NE; e++)
            sc[e] = 1.f / (1.f + expf(-logits[e])) + gb[e];
        int idx[TOPK]; float wv[TOPK]; float sum = 0.f;
        bool used[NE];
        #pragma unroll
        for (int e = 0; e < NE; e++) used[e] = false;
        #pragma unroll
        for (int k = 0; k < TOPK; k++) {
            float best = -1e30f; int bi = 0;
            #pragma unroll
            for (int e = 0; e < NE; e++)
                if (!used[e] && sc[e] > best) { best = sc[e]; bi = e; }
            used[bi] = true; idx[k] = bi; wv[k] = best; sum += best;
        }
        float inv = 1.f / sum;
        #pragma unroll
        for (int k = 0; k < TOPK; k++) {
            int e = idx[k];
            int pos = atomicAdd(&g_counts[e], 1);
            g_entries[e * NT + pos] = t * TOPK + k;
            g_slotw[t * TOPK + k]   = wv[k] * inv;
        }
    }
}

__device__ __forceinline__ float sigmoidf_(float v) { return 1.f / (1.f + expf(-v)); }

// ---------------- asm helpers ----------------
__device__ __forceinline__ uint32_t saddr(const void* p) {
    return (uint32_t)__cvta_generic_to_shared(p);
}
__device__ __forceinline__ void cpa(uint32_t dst, const void* src) {
    asm volatile("cp.async.cg.shared.global [%0], [%1], 16;" :: "r"(dst), "l"(src));
}
__device__ __forceinline__ void cp_commit() { asm volatile("cp.async.commit_group;"); }
__device__ __forceinline__ void cp_wait2()  { asm volatile("cp.async.wait_group 2;"); }
__device__ __forceinline__ void ldsm_x4(uint32_t r[4], uint32_t a) {
    asm volatile("ldmatrix.sync.aligned.m8n8.x4.shared.b16 {%0,%1,%2,%3}, [%4];"
                 : "=r"(r[0]), "=r"(r[1]), "=r"(r[2]), "=r"(r[3]) : "r"(a));
}
__device__ __forceinline__ void ldsm_x4t(uint32_t r[4], uint32_t a) {
    asm volatile("ldmatrix.sync.aligned.m8n8.x4.trans.shared.b16 {%0,%1,%2,%3}, [%4];"
                 : "=r"(r[0]), "=r"(r[1]), "=r"(r[2]), "=r"(r[3]) : "r"(a));
}
__device__ __forceinline__ void mma16816(float c[4], const uint32_t a[4], const uint32_t b[2]) {
    asm volatile("mma.sync.aligned.m16n8k16.row.col.f32.f16.f16.f32 "
                 "{%0,%1,%2,%3}, {%4,%5,%6,%7}, {%8,%9}, {%0,%1,%2,%3};"
                 : "+f"(c[0]), "+f"(c[1]), "+f"(c[2]), "+f"(c[3])
                 : "r"(a[0]), "r"(a[1]), "r"(a[2]), "r"(a[3]), "r"(b[0]), "r"(b[1]));
}

#define APITCH 40     // fp16 elems; 80B rows
#define BP_UP  72     // 144B rows
#define BP_DN  136    // 272B rows
#define A_ST   (128 * APITCH)
#define BU_ST  (32 * BP_UP)
#define BD_ST  (32 * BP_DN)
#define UP_STAGE   ((2 * A_ST + 2 * BU_ST) * 2)   // A hi+lo, B1, B3
#define DOWN_STAGE ((A_ST + BD_ST) * 2)           // A single, B
#define UP_SMEM    (4 * UP_STAGE)
#define DOWN_SMEM  (4 * DOWN_STAGE)

// ================ up: H = f(X@W1, X@W3), tile 128(M) x 64(H cols) ================
template<bool ROUTED>
__global__ __launch_bounds__(256, 1) void up_k(
        const fp16* __restrict__ Xh, const fp16* __restrict__ Xl,
        const fp16* __restrict__ W1, const fp16* __restrict__ W3,
        fp16* __restrict__ O)
{
    int e  = ROUTED ? blockIdx.z : 0;
    int M  = ROUTED ? g_counts[e] : NT;
    int m0 = blockIdx.x * 128;
    if (m0 >= M) return;
    int n0 = blockIdx.y * 64;
    size_t woff = ROUTED ? (size_t)e * DIM * HID : 0;
    const fp16* w1 = W1 + woff;
    const fp16* w3 = W3 + woff;

    extern __shared__ char smem[];
    int tid = threadIdx.x, lane = tid & 31, warp = tid >> 5;
    int wm = (warp & 3) * 32, wn = (warp >> 2) * 32;

    int ar = tid >> 1, ac = (tid & 1) * 16;
    int gr = m0 + ar; if (gr >= M) gr = m0;
    int tok = ROUTED ? (g_entries[e * NT + gr] >> 2) : gr;
    const fp16* srcAh = Xh + (size_t)tok * DIM + ac;
    const fp16* srcAl = Xl + (size_t)tok * DIM + ac;

    int br = tid >> 3, bc = (tid & 7) * 8;
    const fp16* src1 = w1 + (size_t)br * HID + n0 + bc;
    const fp16* src3 = w3 + (size_t)br * HID + n0 + bc;

    uint32_t sb = saddr(smem);
    uint32_t offAh = (uint32_t)(ar * APITCH + ac) * 2;
    uint32_t offAl = offAh + A_ST * 2;
    uint32_t offB1 = (2 * A_ST + br * BP_UP + bc) * 2;
    uint32_t offB3 = offB1 + BU_ST * 2;

    float acc1[2][4][4] = {}, acc3[2][4][4] = {};

    auto load_stage = [&](int st, int k0) {
        uint32_t base = sb + st * UP_STAGE;
        cpa(base + offAh,      srcAh + k0);
        cpa(base + offAh + 16, srcAh + k0 + 8);
        cpa(base + offAl,      srcAl + k0);
        cpa(base + offAl + 16, srcAl + k0 + 8);
        size_t rk = (size_t)k0 * HID;
        cpa(base + offB1, src1 + rk);
        cpa(base + offB3, src3 + rk);
    };

    load_stage(0, 0);      cp_commit();
    load_stage(1, KC);     cp_commit();
    load_stage(2, 2 * KC); cp_commit();

    const int KT = DIM / KC;
    for (int t = 0; t < KT; t++) {
        int st = t & 3;
        cp_wait2();
        __syncthreads();
        if (t + 3 < KT) load_stage((t + 3) & 3, (t + 3) * KC);
        cp_commit();

        uint32_t base = sb + st * UP_STAGE;
        #pragma unroll
        for (int kk = 0; kk < KC; kk += 16) {
            uint32_t ah[2][4], al[2][4];
            #pragma unroll
            for (int mi = 0; mi < 2; mi++) {
                uint32_t ao = ((wm + mi * 16 + (lane & 15)) * APITCH + kk + ((lane >> 4) << 3)) * 2;
                ldsm_x4(ah[mi], base + ao);
                ldsm_x4(al[mi], base + A_ST * 2 + ao);
            }
            uint32_t b1[2][4], b3[2][4];
            #pragma unroll
            for (int g = 0; g < 2; g++) {
                uint32_t bo = ((kk + (lane & 15)) * BP_UP + wn + g * 16 + ((lane >> 4) << 3)) * 2;
                ldsm_x4t(b1[g], base + (2 * A_ST) * 2 + bo);
                ldsm_x4t(b3[g], base + (2 * A_ST + BU_ST) * 2 + bo);
            }
            #pragma unroll
            for (int ni = 0; ni < 4; ni++) {
                int g = ni >> 1, o = (ni & 1) * 2;
                #pragma unroll
                for (int mi = 0; mi < 2; mi++) {
                    mma16816(acc1[mi][ni], ah[mi], &b1[g][o]);
                    mma16816(acc1[mi][ni], al[mi], &b1[g][o]);
                    mma16816(acc3[mi][ni], ah[mi], &b3[g][o]);
                    mma16816(acc3[mi][ni], al[mi], &b3[g][o]);
                }
            }
        }
        __syncthreads();
    }

    #pragma unroll
    for (int mi = 0; mi < 2; mi++)
        #pragma unroll
        for (int half = 0; half < 2; half++) {
            int r = m0 + wm + mi * 16 + (lane >> 2) + half * 8;
            if (r >= M) continue;
            size_t orow = ROUTED ? (size_t)g_entries[e * NT + r] : (size_t)r;
            #pragma unroll
            for (int ni = 0; ni < 4; ni++) {
                float v1a = acc1[mi][ni][half * 2 + 0], v1b = acc1[mi][ni][half * 2 + 1];
                float v3a = acc3[mi][ni][half * 2 + 0], v3b = acc3[mi][ni][half * 2 + 1];
                float oa, ob;
                if (ROUTED) {
                    float pa = v1a * v3a, pb = v1b * v3b;
                    oa = pa * sigmoidf_(pa);
                    ob = pb * sigmoidf_(pb);
                } else {
                    oa = v1a * sigmoidf_(v1a) * v3a;
                    ob = v1b * sigmoidf_(v1b) * v3b;
                }
                __half2 h2;
                h2.x = __float2half_rn(oa);
                h2.y = __float2half_rn(ob);
                *(__half2*)&O[orow * HID + n0 + wn + ni * 8 + ((lane & 3) << 1)] = h2;
            }
        }
}

// ================ down: Y = H @ W2, tile 128(M) x 128(N), single-plane A ========
template<bool ROUTED>
__global__ __launch_bounds__(256) void down_k(
        const fp16* __restrict__ H, const fp16* __restrict__ W2,
        float* __restrict__ out)
{
    int e  = ROUTED ? blockIdx.z : 0;
    int M  = ROUTED ? g_counts[e] : NT;
    int m0 = blockIdx.x * 128;
    if (m0 >= M) return;
    int n0 = blockIdx.y * 128;
    size_t woff = ROUTED ? (size_t)e * HID * DIM : 0;
    const fp16* w2 = W2 + woff;

    extern __shared__ char smem[];
    int tid = threadIdx.x, lane = tid & 31, warp = tid >> 5;
    int wm = (warp & 1) * 64, wn = (warp >> 1) * 32;

    int ar = tid >> 1, ac = (tid & 1) * 16;
    int gr = m0 + ar; if (gr >= M) gr = m0;
    size_t rid = ROUTED ? (size_t)g_entries[e * NT + gr] : (size_t)gr;
    const fp16* srcA = H + rid * HID + ac;

    int br = tid >> 3, bc = (tid & 7) * 16;
    const fp16* srcB = w2 + (size_t)br * DIM + n0 + bc;

    uint32_t sb = saddr(smem);
    uint32_t offA = (uint32_t)(ar * APITCH + ac) * 2;
    uint32_t offB = (A_ST + br * BP_DN + bc) * 2;

    float acc[4][4][4] = {};

    auto load_stage = [&](int st, int k0) {
        uint32_t base = sb + st * DOWN_STAGE;
        cpa(base + offA,      srcA + k0);
        cpa(base + offA + 16, srcA + k0 + 8);
        size_t rk = (size_t)k0 * DIM;
        cpa(base + offB,      srcB + rk);
        cpa(base + offB + 16, srcB + rk + 8);
    };

    load_stage(0, 0);      cp_commit();
    load_stage(1, KC);     cp_commit();
    load_stage(2, 2 * KC); cp_commit();

    const int KT = HID / KC;
    for (int t = 0; t < KT; t++) {
        int st = t & 3;
        cp_wait2();
        __syncthreads();
        if (t + 3 < KT) load_stage((t + 3) & 3, (t + 3) * KC);
        cp_commit();

        uint32_t base = sb + st * DOWN_STAGE;
        #pragma unroll
        for (int kk = 0; kk < KC; kk += 16) {
            uint32_t ah[4][4];
            #pragma unroll
            for (int mi = 0; mi < 4; mi++) {
                uint32_t ao = ((wm + mi * 16 + (lane & 15)) * APITCH + kk + ((lane >> 4) << 3)) * 2;
                ldsm_x4(ah[mi], base + ao);
            }
            uint32_t bh[2][4];
            #pragma unroll
            for (int g = 0; g < 2; g++) {
                uint32_t bo = ((kk + (lane & 15)) * BP_DN + wn + g * 16 + ((lane >> 4) << 3)) * 2;
                ldsm_x4t(bh[g], base + A_ST * 2 + bo);
            }
            #pragma unroll
            for (int ni = 0; ni < 4; ni++) {
                int g = ni >> 1, o = (ni & 1) * 2;
                #pragma unroll
                for (int mi = 0; mi < 4; mi++)
                    mma16816(acc[mi][ni], ah[mi], &bh[g][o]);
            }
        }
        __syncthreads();
    }

    #pragma unroll
    for (int mi = 0; mi < 4; mi++)
        #pragma unroll
        for (int half = 0; half < 2; half++) {
            int r = m0 + wm + mi * 16 + (lane >> 2) + half * 8;
            if (r >= M) continue;
            if (ROUTED) {
                int slot = g_entries[e * NT + r];
                int tok  = slot >> 2;
                float w  = g_slotw[slot];
                #pragma unroll
                for (int ni = 0; ni < 4; ni++) {
                    int col = n0 + wn + ni * 8 + ((lane & 3) << 1);
                    atomicAdd(&out[(size_t)tok * DIM + col],     acc[mi][ni][half * 2 + 0] * w);
                    atomicAdd(&out[(size_t)tok * DIM + col + 1], acc[mi][ni][half * 2 + 1] * w);
                }
            } else {
                #pragma unroll
                for (int ni = 0; ni < 4; ni++) {
                    float2 o;
                    o.x = acc[mi][ni][half * 2 + 0];
                    o.y = acc[mi][ni][half * 2 + 1];
                    *(float2*)&out[(size_t)r * DIM + n0 + wn + ni * 8 + ((lane & 3) << 1)] = o;
                }
            }
        }
}

static void* sym(const void* s) { void* p; cudaGetSymbolAddress(&p, s); return p; }

extern "C" void kernel_launch(void* const* d_in, const int* in_sizes, int n_in,
                              void* d_out, int out_size)
{
    (void)in_sizes; (void)n_in; (void)out_size;
    const float* x   = (const float*)d_in[0];
    const float* gw  = (const float*)d_in[1];
    const float* gb  = (const float*)d_in[2];
    const float* w1s = (const float*)d_in[3];
    const float* w2s = (const float*)d_in[4];
    const float* w3s = (const float*)d_in[5];
    const float* w1r = (const float*)d_in[6];
    const float* w2r = (const float*)d_in[7];
    const float* w3r = (const float*)d_in[8];
    float* out = (float*)d_out;

    fp16 *xh = (fp16*)sym(g_xh), *xl = (fp16*)sym(g_xl);
    fp16 *pw1s = (fp16*)sym(g_w1s), *pw3s = (fp16*)sym(g_w3s), *pw2s = (fp16*)sym(g_w2s);
    fp16 *pw1r = (fp16*)sym(g_w1r), *pw3r = (fp16*)sym(g_w3r), *pw2r = (fp16*)sym(g_w2r);
    fp16 *Hs = (fp16*)sym(g_Hs), *Hr = (fp16*)sym(g_Hr);

    cudaFuncSetAttribute(up_k<false>,  cudaFuncAttributeMaxDynamicSharedMemorySize, UP_SMEM);
    cudaFuncSetAttribute(up_k<true>,   cudaFuncAttributeMaxDynamicSharedMemorySize, UP_SMEM);
    cudaFuncSetAttribute(down_k<false>, cudaFuncAttributeMaxDynamicSharedMemorySize, DOWN_SMEM);
    cudaFuncSetAttribute(down_k<true>,  cudaFuncAttributeMaxDynamicSharedMemorySize, DOWN_SMEM);

    auto cvt = [&](const float* s, fp16* d, size_t n) {
        int n4 = (int)(n / 4);
        int blocks = min((n4 + 1023) / 1024, 8192);
        cvt_kernel<<<blocks, 256>>>(s, d, n4);
    };

    zero_counts_kernel<<<1, 32>>>();
    gate_kernel<<<NT, 256>>>(x, gw, gb);

    {
        int n4 = (int)((size_t)NT * DIM / 4);
        split_kernel<<<(n4 + 1023) / 1024, 256>>>(x, xh, xl, n4);
    }
    cvt(w1s, pw1s, (size_t)DIM * HID);
    cvt(w3s, pw3s, (size_t)DIM * HID);
    cvt(w2s, pw2s, (size_t)HID * DIM);
    cvt(w1r, pw1r, (size_t)NE * DIM * HID);
    cvt(w3r, pw3r, (size_t)NE * DIM * HID);
    cvt(w2r, pw2r, (size_t)NE * HID * DIM);

    // shared expert
    up_k<false><<<dim3(NT / 128, HID / 64), 256, UP_SMEM>>>(xh, xl, pw1s, pw3s, Hs);
    down_k<false><<<dim3(NT / 128, DIM / 128), 256, DOWN_SMEM>>>(Hs, pw2s, out);

    // routed experts
    up_k<true><<<dim3(NT / 128, HID / 64, NE), 256, UP_SMEM>>>(xh, xl, pw1r, pw3r, Hr);
    down_k<true><<<dim3(NT / 128, DIM / 128, NE), 256, DOWN_SMEM>>>(Hr, pw2r, out);
}

// round 7
// speedup vs baseline: 3.8350x; 1.1317x over previous
#include <cuda_runtime.h>
#include <cuda_fp16.h>
#include <math.h>
#include <stdint.h>

#define NT   2048
#define DIM  2048
#define HID  1408
#define NE   16
#define TOPK 4
#define KC   32

typedef __half fp16;

// ---- routing scratch ----
__device__ int   g_counts[NE];
__device__ int   g_entries[NE * NT];
__device__ float g_slotw[NT * TOPK];

// ---- fp16 planes ----
__device__ fp16 g_xh[NT * DIM], g_xl[NT * DIM];
__device__ fp16 g_w1s[DIM * HID], g_w3s[DIM * HID], g_w2s[HID * DIM];
__device__ fp16 g_w1r[(size_t)NE * DIM * HID];
__device__ fp16 g_w3r[(size_t)NE * DIM * HID];
__device__ fp16 g_w2r[(size_t)NE * HID * DIM];
__device__ fp16 g_Hs[(size_t)NT * HID];
__device__ fp16 g_Hr[(size_t)NT * TOPK * HID];

__global__ void zero_counts_kernel() {
    if (threadIdx.x < NE) g_counts[threadIdx.x] = 0;
}

__device__ __forceinline__ uint32_t h2u(float a, float b) {
    __half2 h = __floats2half2_rn(a, b);
    return *(uint32_t*)&h;
}

// ---- fp32 -> fp16 convert (weights): 8 float4 loads -> 4 uint4 stores / iter ----
// P = number of uint4 outputs (= n_elems/8); requires P % 4 == 0 (true for all sizes here)
__global__ __launch_bounds__(256) void cvt_kernel(const float4* __restrict__ src,
                                                  uint4* __restrict__ dst, int P)
{
    int gid = blockIdx.x * blockDim.x + threadIdx.x;
    int stride = gridDim.x * blockDim.x;
    for (int p = gid * 4; p < P; p += stride * 4) {
        float4 v[8];
        #pragma unroll
        for (int j = 0; j < 8; j++) v[j] = __ldcs(src + p * 2 + j);
        #pragma unroll
        for (int j = 0; j < 4; j++) {
            uint4 o;
            o.x = h2u(v[2*j].x,   v[2*j].y);
            o.y = h2u(v[2*j].z,   v[2*j].w);
            o.z = h2u(v[2*j+1].x, v[2*j+1].y);
            o.w = h2u(v[2*j+1].z, v[2*j+1].w);
            __stcs(dst + p + j, o);
        }
    }
}

// ---- fp32 -> fp16 hi/lo split (x): 4 float4 loads -> 2+2 uint4 stores / iter ----
__global__ __launch_bounds__(256) void split_kernel(const float4* __restrict__ src,
                                                    uint4* __restrict__ hi,
                                                    uint4* __restrict__ lo, int P)
{
    int gid = blockIdx.x * blockDim.x + threadIdx.x;
    int stride = gridDim.x * blockDim.x;
    for (int p = gid * 2; p < P; p += stride * 2) {
        float4 v[4];
        #pragma unroll
        for (int j = 0; j < 4; j++) v[j] = __ldcs(src + p * 2 + j);
        #pragma unroll
        for (int j = 0; j < 2; j++) {
            float f[8] = { v[2*j].x, v[2*j].y, v[2*j].z, v[2*j].w,
                           v[2*j+1].x, v[2*j+1].y, v[2*j+1].z, v[2*j+1].w };
            float h[8], l[8];
            #pragma unroll
            for (int q = 0; q < 8; q++) {
                h[q] = __half2float(__float2half_rn(f[q]));
                l[q] = f[q] - h[q];
            }
            uint4 oh, ol;
            oh.x = h2u(h[0], h[1]); oh.y = h2u(h[2], h[3]);
            oh.z = h2u(h[4], h[5]); oh.w = h2u(h[6], h[7]);
            ol.x = h2u(l[0], l[1]); ol.y = h2u(l[2], l[3]);
            ol.z = h2u(l[4], l[5]); ol.w = h2u(l[6], l[7]);
            __stcs(hi + p + j, oh);
            __stcs(lo + p + j, ol);
        }
    }
}

// ---------------- gate ----------------
__global__ __launch_bounds__(256) void gate_kernel(const float* __restrict__ x,
                                                   const float* __restrict__ gw,
                                                   const float* __restrict__ gb)
{
    int t = blockIdx.x;
    __shared__ float xs[DIM];
    for (int i = threadIdx.x; i < DIM; i += blockDim.x)
        xs[i] = x[(size_t)t * DIM + i];
    __syncthreads();

    __shared__ float logits[NE];
    int warp = threadIdx.x >> 5, lane = threadIdx.x & 31;
    for (int e = warp; e < NE; e += 8) {
        const float* w = gw + (size_t)e * DIM;
        float s = 0.f;
        for (int d = lane; d < DIM; d += 32) s += w[d] * xs[d];
        #pragma unroll
        for (int o = 16; o > 0; o >>= 1) s += __shfl_down_sync(0xffffffffu, s, o);
        if (lane == 0) logits[e] = s;
    }
    __syncthreads();

    if (threadIdx.x == 0) {
        float sc[NE];
        #pragma unroll
        for (int e = 0; e < NE; e++)
            sc[e] = 1.f / (1.f + expf(-logits[e])) + gb[e];
        int idx[TOPK]; float wv[TOPK]; float sum = 0.f;
        bool used[NE];
        #pragma unroll
        for (int e = 0; e < NE; e++) used[e] = false;
        #pragma unroll
        for (int k = 0; k < TOPK; k++) {
            float best = -1e30f; int bi = 0;
            #pragma unroll
            for (int e = 0; e < NE; e++)
                if (!used[e] && sc[e] > best) { best = sc[e]; bi = e; }
            used[bi] = true; idx[k] = bi; wv[k] = best; sum += best;
        }
        float inv = 1.f / sum;
        #pragma unroll
        for (int k = 0; k < TOPK; k++) {
            int e = idx[k];
            int pos = atomicAdd(&g_counts[e], 1);
            g_entries[e * NT + pos] = t * TOPK + k;
            g_slotw[t * TOPK + k]   = wv[k] * inv;
        }
    }
}

__device__ __forceinline__ float sigmoidf_(float v) { return 1.f / (1.f + expf(-v)); }

// ---------------- asm helpers ----------------
__device__ __forceinline__ uint32_t saddr(const void* p) {
    return (uint32_t)__cvta_generic_to_shared(p);
}
__device__ __forceinline__ void cpa(uint32_t dst, const void* src) {
    asm volatile("cp.async.cg.shared.global [%0], [%1], 16;" :: "r"(dst), "l"(src));
}
__device__ __forceinline__ void cp_commit() { asm volatile("cp.async.commit_group;"); }
__device__ __forceinline__ void cp_wait1()  { asm volatile("cp.async.wait_group 1;"); }
__device__ __forceinline__ void cp_wait2()  { asm volatile("cp.async.wait_group 2;"); }
__device__ __forceinline__ void ldsm_x4(uint32_t r[4], uint32_t a) {
    asm volatile("ldmatrix.sync.aligned.m8n8.x4.shared.b16 {%0,%1,%2,%3}, [%4];"
                 : "=r"(r[0]), "=r"(r[1]), "=r"(r[2]), "=r"(r[3]) : "r"(a));
}
__device__ __forceinline__ void ldsm_x4t(uint32_t r[4], uint32_t a) {
    asm volatile("ldmatrix.sync.aligned.m8n8.x4.trans.shared.b16 {%0,%1,%2,%3}, [%4];"
                 : "=r"(r[0]), "=r"(r[1]), "=r"(r[2]), "=r"(r[3]) : "r"(a));
}
__device__ __forceinline__ void mma16816(float c[4], const uint32_t a[4], const uint32_t b[2]) {
    asm volatile("mma.sync.aligned.m16n8k16.row.col.f32.f16.f16.f32 "
                 "{%0,%1,%2,%3}, {%4,%5,%6,%7}, {%8,%9}, {%0,%1,%2,%3};"
                 : "+f"(c[0]), "+f"(c[1]), "+f"(c[2]), "+f"(c[3])
                 : "r"(a[0]), "r"(a[1]), "r"(a[2]), "r"(a[3]), "r"(b[0]), "r"(b[1]));
}

#define APITCH 40
#define BP_UP  72
#define BP_DN  136
#define A_ST   (128 * APITCH)
#define BU_ST  (32 * BP_UP)
#define BD_ST  (32 * BP_DN)
#define UP_STAGE   ((2 * A_ST + 2 * BU_ST) * 2)
#define DOWN_STAGE ((A_ST + BD_ST) * 2)
#define UP_SMEM    (3 * UP_STAGE)     // 3-stage: 89 KB -> 2 CTAs/SM
#define DOWN_SMEM  (4 * DOWN_STAGE)   // 4-stage: 75.8 KB -> 2 CTAs/SM

// ================ up: H = f(X@W1, X@W3), tile 128(M) x 64(H cols) ================
template<bool ROUTED>
__global__ __launch_bounds__(256, 2) void up_k(
        const fp16* __restrict__ Xh, const fp16* __restrict__ Xl,
        const fp16* __restrict__ W1, const fp16* __restrict__ W3,
        fp16* __restrict__ O)
{
    int e  = ROUTED ? blockIdx.z : 0;
    int M  = ROUTED ? g_counts[e] : NT;
    int m0 = blockIdx.x * 128;
    if (m0 >= M) return;
    int n0 = blockIdx.y * 64;
    size_t woff = ROUTED ? (size_t)e * DIM * HID : 0;
    const fp16* w1 = W1 + woff;
    const fp16* w3 = W3 + woff;

    extern __shared__ char smem[];
    int tid = threadIdx.x, lane = tid & 31, warp = tid >> 5;
    int wm = (warp & 3) * 32, wn = (warp >> 2) * 32;

    int ar = tid >> 1, ac = (tid & 1) * 16;
    int gr = m0 + ar; if (gr >= M) gr = m0;
    int tok = ROUTED ? (g_entries[e * NT + gr] >> 2) : gr;
    const fp16* srcAh = Xh + (size_t)tok * DIM + ac;
    const fp16* srcAl = Xl + (size_t)tok * DIM + ac;

    int br = tid >> 3, bc = (tid & 7) * 8;
    const fp16* src1 = w1 + (size_t)br * HID + n0 + bc;
    const fp16* src3 = w3 + (size_t)br * HID + n0 + bc;

    uint32_t sb = saddr(smem);
    uint32_t offAh = (uint32_t)(ar * APITCH + ac) * 2;
    uint32_t offAl = offAh + A_ST * 2;
    uint32_t offB1 = (2 * A_ST + br * BP_UP + bc) * 2;
    uint32_t offB3 = offB1 + BU_ST * 2;

    float acc1[2][4][4] = {}, acc3[2][4][4] = {};

    auto load_stage = [&](int st, int k0) {
        uint32_t base = sb + st * UP_STAGE;
        cpa(base + offAh,      srcAh + k0);
        cpa(base + offAh + 16, srcAh + k0 + 8);
        cpa(base + offAl,      srcAl + k0);
        cpa(base + offAl + 16, srcAl + k0 + 8);
        size_t rk = (size_t)k0 * HID;
        cpa(base + offB1, src1 + rk);
        cpa(base + offB3, src3 + rk);
    };

    load_stage(0, 0);  cp_commit();
    load_stage(1, KC); cp_commit();

    const int KT = DIM / KC;
    int st = 0;
    for (int t = 0; t < KT; t++) {
        cp_wait1();
        __syncthreads();
        int nst = st + 2; if (nst >= 3) nst -= 3;
        if (t + 2 < KT) load_stage(nst, (t + 2) * KC);
        cp_commit();

        uint32_t base = sb + st * UP_STAGE;
        #pragma unroll
        for (int kk = 0; kk < KC; kk += 16) {
            uint32_t ah[2][4], al[2][4];
            #pragma unroll
            for (int mi = 0; mi < 2; mi++) {
                uint32_t ao = ((wm + mi * 16 + (lane & 15)) * APITCH + kk + ((lane >> 4) << 3)) * 2;
                ldsm_x4(ah[mi], base + ao);
                ldsm_x4(al[mi], base + A_ST * 2 + ao);
            }
            uint32_t b1[2][4], b3[2][4];
            #pragma unroll
            for (int g = 0; g < 2; g++) {
                uint32_t bo = ((kk + (lane & 15)) * BP_UP + wn + g * 16 + ((lane >> 4) << 3)) * 2;
                ldsm_x4t(b1[g], base + (2 * A_ST) * 2 + bo);
                ldsm_x4t(b3[g], base + (2 * A_ST + BU_ST) * 2 + bo);
            }
            #pragma unroll
            for (int ni = 0; ni < 4; ni++) {
                int g = ni >> 1, o = (ni & 1) * 2;
                #pragma unroll
                for (int mi = 0; mi < 2; mi++) {
                    mma16816(acc1[mi][ni], ah[mi], &b1[g][o]);
                    mma16816(acc1[mi][ni], al[mi], &b1[g][o]);
                    mma16816(acc3[mi][ni], ah[mi], &b3[g][o]);
                    mma16816(acc3[mi][ni], al[mi], &b3[g][o]);
                }
            }
        }
        __syncthreads();
        if (++st == 3) st = 0;
    }

    #pragma unroll
    for (int mi = 0; mi < 2; mi++)
        #pragma unroll
        for (int half = 0; half < 2; half++) {
            int r = m0 + wm + mi * 16 + (lane >> 2) + half * 8;
            if (r >= M) continue;
            size_t orow = ROUTED ? (size_t)g_entries[e * NT + r] : (size_t)r;
            #pragma unroll
            for (int ni = 0; ni < 4; ni++) {
                float v1a = acc1[mi][ni][half * 2 + 0], v1b = acc1[mi][ni][half * 2 + 1];
                float v3a = acc3[mi][ni][half * 2 + 0], v3b = acc3[mi][ni][half * 2 + 1];
                float oa, ob;
                if (ROUTED) {
                    float pa = v1a * v3a, pb = v1b * v3b;
                    oa = pa * sigmoidf_(pa);
                    ob = pb * sigmoidf_(pb);
                } else {
                    oa = v1a * sigmoidf_(v1a) * v3a;
                    ob = v1b * sigmoidf_(v1b) * v3b;
                }
                __half2 h2 = __floats2half2_rn(oa, ob);
                *(__half2*)&O[orow * HID + n0 + wn + ni * 8 + ((lane & 3) << 1)] = h2;
            }
        }
}

// ================ down: Y = H @ W2, tile 128(M) x 128(N), single-plane A ========
template<bool ROUTED>
__global__ __launch_bounds__(256, 2) void down_k(
        const fp16* __restrict__ H, const fp16* __restrict__ W2,
        float* __restrict__ out)
{
    int e  = ROUTED ? blockIdx.z : 0;
    int M  = ROUTED ? g_counts[e] : NT;
    int m0 = blockIdx.x * 128;
    if (m0 >= M) return;
    int n0 = blockIdx.y * 128;
    size_t woff = ROUTED ? (size_t)e * HID * DIM : 0;
    const fp16* w2 = W2 + woff;

    extern __shared__ char smem[];
    int tid = threadIdx.x, lane = tid & 31, warp = tid >> 5;
    int wm = (warp & 1) * 64, wn = (warp >> 1) * 32;

    int ar = tid >> 1, ac = (tid & 1) * 16;
    int gr = m0 + ar; if (gr >= M) gr = m0;
    size_t rid = ROUTED ? (size_t)g_entries[e * NT + gr] : (size_t)gr;
    const fp16* srcA = H + rid * HID + ac;

    int br = tid >> 3, bc = (tid & 7) * 16;
    const fp16* srcB = w2 + (size_t)br * DIM + n0 + bc;

    uint32_t sb = saddr(smem);
    uint32_t offA = (uint32_t)(ar * APITCH + ac) * 2;
    uint32_t offB = (A_ST + br * BP_DN + bc) * 2;

    float acc[4][4][4] = {};

    auto load_stage = [&](int st, int k0) {
        uint32_t base = sb + st * DOWN_STAGE;
        cpa(base + offA,      srcA + k0);
        cpa(base + offA + 16, srcA + k0 + 8);
        size_t rk = (size_t)k0 * DIM;
        cpa(base + offB,      srcB + rk);
        cpa(base + offB + 16, srcB + rk + 8);
    };

    load_stage(0, 0);      cp_commit();
    load_stage(1, KC);     cp_commit();
    load_stage(2, 2 * KC); cp_commit();

    const int KT = HID / KC;
    for (int t = 0; t < KT; t++) {
        int st = t & 3;
        cp_wait2();
        __syncthreads();
        if (t + 3 < KT) load_stage((t + 3) & 3, (t + 3) * KC);
        cp_commit();

        uint32_t base = sb + st * DOWN_STAGE;
        #pragma unroll
        for (int kk = 0; kk < KC; kk += 16) {
            uint32_t ah[4][4];
            #pragma unroll
            for (int mi = 0; mi < 4; mi++) {
                uint32_t ao = ((wm + mi * 16 + (lane & 15)) * APITCH + kk + ((lane >> 4) << 3)) * 2;
                ldsm_x4(ah[mi], base + ao);
            }
            uint32_t bh[2][4];
            #pragma unroll
            for (int g = 0; g < 2; g++) {
                uint32_t bo = ((kk + (lane & 15)) * BP_DN + wn + g * 16 + ((lane >> 4) << 3)) * 2;
                ldsm_x4t(bh[g], base + A_ST * 2 + bo);
            }
            #pragma unroll
            for (int ni = 0; ni < 4; ni++) {
                int g = ni >> 1, o = (ni & 1) * 2;
                #pragma unroll
                for (int mi = 0; mi < 4; mi++)
                    mma16816(acc[mi][ni], ah[mi], &bh[g][o]);
            }
        }
        __syncthreads();
    }

    #pragma unroll
    for (int mi = 0; mi < 4; mi++)
        #pragma unroll
        for (int half = 0; half < 2; half++) {
            int r = m0 + wm + mi * 16 + (lane >> 2) + half * 8;
            if (r >= M) continue;
            if (ROUTED) {
                int slot = g_entries[e * NT + r];
                int tok  = slot >> 2;
                float w  = g_slotw[slot];
                #pragma unroll
                for (int ni = 0; ni < 4; ni++) {
                    int col = n0 + wn + ni * 8 + ((lane & 3) << 1);
                    atomicAdd(&out[(size_t)tok * DIM + col],     acc[mi][ni][half * 2 + 0] * w);
                    atomicAdd(&out[(size_t)tok * DIM + col + 1], acc[mi][ni][half * 2 + 1] * w);
                }
            } else {
                #pragma unroll
                for (int ni = 0; ni < 4; ni++) {
                    float2 o;
                    o.x = acc[mi][ni][half * 2 + 0];
                    o.y = acc[mi][ni][half * 2 + 1];
                    *(float2*)&out[(size_t)r * DIM + n0 + wn + ni * 8 + ((lane & 3) << 1)] = o;
                }
            }
        }
}

static void* sym(const void* s) { void* p; cudaGetSymbolAddress(&p, s); return p; }

extern "C" void kernel_launch(void* const* d_in, const int* in_sizes, int n_in,
                              void* d_out, int out_size)
{
    (void)in_sizes; (void)n_in; (void)out_size;
    const float* x   = (const float*)d_in[0];
    const float* gw  = (const float*)d_in[1];
    const float* gb  = (const float*)d_in[2];
    const float* w1s = (const float*)d_in[3];
    const float* w2s = (const float*)d_in[4];
    const float* w3s = (const float*)d_in[5];
    const float* w1r = (const float*)d_in[6];
    const float* w2r = (const float*)d_in[7];
    const float* w3r = (const float*)d_in[8];
    float* out = (float*)d_out;

    fp16 *xh = (fp16*)sym(g_xh), *xl = (fp16*)sym(g_xl);
    fp16 *pw1s = (fp16*)sym(g_w1s), *pw3s = (fp16*)sym(g_w3s), *pw2s = (fp16*)sym(g_w2s);
    fp16 *pw1r = (fp16*)sym(g_w1r), *pw3r = (fp16*)sym(g_w3r), *pw2r = (fp16*)sym(g_w2r);
    fp16 *Hs = (fp16*)sym(g_Hs), *Hr = (fp16*)sym(g_Hr);

    cudaFuncSetAttribute(up_k<false>,  cudaFuncAttributeMaxDynamicSharedMemorySize, UP_SMEM);
    cudaFuncSetAttribute(up_k<true>,   cudaFuncAttributeMaxDynamicSharedMemorySize, UP_SMEM);
    cudaFuncSetAttribute(down_k<false>, cudaFuncAttributeMaxDynamicSharedMemorySize, DOWN_SMEM);
    cudaFuncSetAttribute(down_k<true>,  cudaFuncAttributeMaxDynamicSharedMemorySize, DOWN_SMEM);

    auto cvt = [&](const float* s, fp16* d, size_t n) {
        int P = (int)(n / 8);
        int blocks = min((P / 4 + 255) / 256, 16384);
        cvt_kernel<<<blocks, 256>>>((const float4*)s, (uint4*)d, P);
    };

    zero_counts_kernel<<<1, 32>>>();
    gate_kernel<<<NT, 256>>>(x, gw, gb);

    {
        int P = (int)((size_t)NT * DIM / 8);
        int blocks = min((P / 2 + 255) / 256, 16384);
        split_kernel<<<blocks, 256>>>((const float4*)x, (uint4*)xh, (uint4*)xl, P);
    }
    cvt(w1s, pw1s, (size_t)DIM * HID);
    cvt(w3s, pw3s, (size_t)DIM * HID);
    cvt(w2s, pw2s, (size_t)HID * DIM);
    cvt(w1r, pw1r, (size_t)NE * DIM * HID);
    cvt(w3r, pw3r, (size_t)NE * DIM * HID);
    cvt(w2r, pw2r, (size_t)NE * HID * DIM);

    // shared expert
    up_k<false><<<dim3(NT / 128, HID / 64), 256, UP_SMEM>>>(xh, xl, pw1s, pw3s, Hs);
    down_k<false><<<dim3(NT / 128, DIM / 128), 256, DOWN_SMEM>>>(Hs, pw2s, out);

    // routed experts
    up_k<true><<<dim3(NT / 128, HID / 64, NE), 256, UP_SMEM>>>(xh, xl, pw1r, pw3r, Hr);
    down_k<true><<<dim3(NT / 128, DIM / 128, NE), 256, DOWN_SMEM>>>(Hr, pw2r, out);
}

// round 8
// speedup vs baseline: 3.9793x; 1.0376x over previous
#include <cuda_runtime.h>
#include <cuda_fp16.h>
#include <math.h>
#include <stdint.h>

#define NT   2048
#define DIM  2048
#define HID  1408
#define NE   16
#define TOPK 4
#define KC   32

typedef __half fp16;

// ---- routing scratch ----
__device__ int   g_counts[NE];
__device__ int   g_entries[NE * NT];
__device__ float g_slotw[NT * TOPK];

// ---- fp16 planes ----
__device__ fp16 g_xh[NT * DIM], g_xl[NT * DIM];
__device__ fp16 g_w1s[DIM * HID], g_w3s[DIM * HID], g_w2s[HID * DIM];
__device__ fp16 g_w1r[(size_t)NE * DIM * HID];
__device__ fp16 g_w3r[(size_t)NE * DIM * HID];
__device__ fp16 g_w2r[(size_t)NE * HID * DIM];
__device__ fp16 g_Hs[(size_t)NT * HID];
__device__ fp16 g_Hr[(size_t)NT * TOPK * HID];

__global__ void zero_counts_kernel() {
    if (threadIdx.x < NE) g_counts[threadIdx.x] = 0;
}

__device__ __forceinline__ uint32_t h2u(float a, float b) {
    __half2 h = __floats2half2_rn(a, b);
    return *(uint32_t*)&h;
}

// ---- fp32 -> fp16 convert: warp-interleaved, MLP 8, fully coalesced ----
// n4 = float4 count; launched with gridDim*blockDim*8 == n4 exactly.
__global__ __launch_bounds__(256) void cvt_kernel(const float4* __restrict__ src,
                                                  uint2* __restrict__ dst)
{
    int stride = gridDim.x * blockDim.x;
    int i = blockIdx.x * blockDim.x + threadIdx.x;
    float4 v[8];
    #pragma unroll
    for (int j = 0; j < 8; j++) v[j] = __ldcs(src + i + j * stride);
    #pragma unroll
    for (int j = 0; j < 8; j++) {
        uint2 o;
        o.x = h2u(v[j].x, v[j].y);
        o.y = h2u(v[j].z, v[j].w);
        __stcs(dst + i + j * stride, o);
    }
}

// ---- fp32 -> fp16 hi/lo split (x): warp-interleaved, MLP 8 ----
__global__ __launch_bounds__(256) void split_kernel(const float4* __restrict__ src,
                                                    uint2* __restrict__ hi,
                                                    uint2* __restrict__ lo)
{
    int stride = gridDim.x * blockDim.x;
    int i = blockIdx.x * blockDim.x + threadIdx.x;
    float4 v[8];
    #pragma unroll
    for (int j = 0; j < 8; j++) v[j] = __ldcs(src + i + j * stride);
    #pragma unroll
    for (int j = 0; j < 8; j++) {
        float f[4] = { v[j].x, v[j].y, v[j].z, v[j].w };
        float h[4], l[4];
        #pragma unroll
        for (int q = 0; q < 4; q++) {
            h[q] = __half2float(__float2half_rn(f[q]));
            l[q] = f[q] - h[q];
        }
        uint2 oh, ol;
        oh.x = h2u(h[0], h[1]); oh.y = h2u(h[2], h[3]);
        ol.x = h2u(l[0], l[1]); ol.y = h2u(l[2], l[3]);
        __stcs(hi + i + j * stride, oh);
        __stcs(lo + i + j * stride, ol);
    }
}

// ---------------- gate ----------------
__global__ __launch_bounds__(256) void gate_kernel(const float* __restrict__ x,
                                                   const float* __restrict__ gw,
                                                   const float* __restrict__ gb)
{
    int t = blockIdx.x;
    __shared__ float xs[DIM];
    for (int i = threadIdx.x; i < DIM; i += blockDim.x)
        xs[i] = x[(size_t)t * DIM + i];
    __syncthreads();

    __shared__ float logits[NE];
    int warp = threadIdx.x >> 5, lane = threadIdx.x & 31;
    for (int e = warp; e < NE; e += 8) {
        const float* w = gw + (size_t)e * DIM;
        float s = 0.f;
        for (int d = lane; d < DIM; d += 32) s += w[d] * xs[d];
        #pragma unroll
        for (int o = 16; o > 0; o >>= 1) s += __shfl_down_sync(0xffffffffu, s, o);
        if (lane == 0) logits[e] = s;
    }
    __syncthreads();

    if (threadIdx.x == 0) {
        float sc[NE];
        #pragma unroll
        for (int e = 0; e < NE; e++)
            sc[e] = 1.f / (1.f + expf(-logits[e])) + gb[e];
        int idx[TOPK]; float wv[TOPK]; float sum = 0.f;
        bool used[NE];
        #pragma unroll
        for (int e = 0; e < NE; e++) used[e] = false;
        #pragma unroll
        for (int k = 0; k < TOPK; k++) {
            float best = -1e30f; int bi = 0;
            #pragma unroll
            for (int e = 0; e < NE; e++)
                if (!used[e] && sc[e] > best) { best = sc[e]; bi = e; }
            used[bi] = true; idx[k] = bi; wv[k] = best; sum += best;
        }
        float inv = 1.f / sum;
        #pragma unroll
        for (int k = 0; k < TOPK; k++) {
            int e = idx[k];
            int pos = atomicAdd(&g_counts[e], 1);
            g_entries[e * NT + pos] = t * TOPK + k;
            g_slotw[t * TOPK + k]   = wv[k] * inv;
        }
    }
}

__device__ __forceinline__ float sigmoidf_(float v) { return 1.f / (1.f + expf(-v)); }

// ---------------- asm helpers ----------------
__device__ __forceinline__ uint32_t saddr(const void* p) {
    return (uint32_t)__cvta_generic_to_shared(p);
}
__device__ __forceinline__ void cpa(uint32_t dst, const void* src) {
    asm volatile("cp.async.cg.shared.global [%0], [%1], 16;" :: "r"(dst), "l"(src));
}
__device__ __forceinline__ void cp_commit() { asm volatile("cp.async.commit_group;"); }
__device__ __forceinline__ void cp_wait1()  { asm volatile("cp.async.wait_group 1;"); }
__device__ __forceinline__ void cp_wait2()  { asm volatile("cp.async.wait_group 2;"); }
__device__ __forceinline__ void ldsm_x4(uint32_t r[4], uint32_t a) {
    asm volatile("ldmatrix.sync.aligned.m8n8.x4.shared.b16 {%0,%1,%2,%3}, [%4];"
                 : "=r"(r[0]), "=r"(r[1]), "=r"(r[2]), "=r"(r[3]) : "r"(a));
}
__device__ __forceinline__ void ldsm_x4t(uint32_t r[4], uint32_t a) {
    asm volatile("ldmatrix.sync.aligned.m8n8.x4.trans.shared.b16 {%0,%1,%2,%3}, [%4];"
                 : "=r"(r[0]), "=r"(r[1]), "=r"(r[2]), "=r"(r[3]) : "r"(a));
}
__device__ __forceinline__ void mma16816(float c[4], const uint32_t a[4], const uint32_t b[2]) {
    asm volatile("mma.sync.aligned.m16n8k16.row.col.f32.f16.f16.f32 "
                 "{%0,%1,%2,%3}, {%4,%5,%6,%7}, {%8,%9}, {%0,%1,%2,%3};"
                 : "+f"(c[0]), "+f"(c[1]), "+f"(c[2]), "+f"(c[3])
                 : "r"(a[0]), "r"(a[1]), "r"(a[2]), "r"(a[3]), "r"(b[0]), "r"(b[1]));
}

#define APITCH 40
#define BP_UP  72
#define BP_DN  136
#define A_ST   (128 * APITCH)
#define BU_ST  (32 * BP_UP)
#define BD_ST  (32 * BP_DN)
#define UP_STAGE   ((2 * A_ST + 2 * BU_ST) * 2)
#define DOWN_STAGE ((A_ST + BD_ST) * 2)
#define UP_SMEM    (3 * UP_STAGE)     // 89 KB -> 2 CTAs/SM
#define DOWN_SMEM  (4 * DOWN_STAGE)   // 75.8 KB -> 2 CTAs/SM

// ================ up: H = f(X@W1, X@W3), tile 128(M) x 64(H cols) ================
template<bool ROUTED>
__global__ __launch_bounds__(256, 2) void up_k(
        const fp16* __restrict__ Xh, const fp16* __restrict__ Xl,
        const fp16* __restrict__ W1, const fp16* __restrict__ W3,
        fp16* __restrict__ O)
{
    int e  = ROUTED ? blockIdx.z : 0;
    int M  = ROUTED ? g_counts[e] : NT;
    int m0 = blockIdx.x * 128;
    if (m0 >= M) return;
    int n0 = blockIdx.y * 64;
    size_t woff = ROUTED ? (size_t)e * DIM * HID : 0;
    const fp16* w1 = W1 + woff;
    const fp16* w3 = W3 + woff;

    extern __shared__ char smem[];
    int tid = threadIdx.x, lane = tid & 31, warp = tid >> 5;
    int wm = (warp & 3) * 32, wn = (warp >> 2) * 32;

    int ar = tid >> 1, ac = (tid & 1) * 16;
    int gr = m0 + ar; if (gr >= M) gr = m0;
    int tok = ROUTED ? (g_entries[e * NT + gr] >> 2) : gr;
    const fp16* srcAh = Xh + (size_t)tok * DIM + ac;
    const fp16* srcAl = Xl + (size_t)tok * DIM + ac;

    int br = tid >> 3, bc = (tid & 7) * 8;
    const fp16* src1 = w1 + (size_t)br * HID + n0 + bc;
    const fp16* src3 = w3 + (size_t)br * HID + n0 + bc;

    uint32_t sb = saddr(smem);
    uint32_t offAh = (uint32_t)(ar * APITCH + ac) * 2;
    uint32_t offAl = offAh + A_ST * 2;
    uint32_t offB1 = (2 * A_ST + br * BP_UP + bc) * 2;
    uint32_t offB3 = offB1 + BU_ST * 2;

    float acc1[2][4][4] = {}, acc3[2][4][4] = {};

    auto load_stage = [&](int st, int k0) {
        uint32_t base = sb + st * UP_STAGE;
        cpa(base + offAh,      srcAh + k0);
        cpa(base + offAh + 16, srcAh + k0 + 8);
        cpa(base + offAl,      srcAl + k0);
        cpa(base + offAl + 16, srcAl + k0 + 8);
        size_t rk = (size_t)k0 * HID;
        cpa(base + offB1, src1 + rk);
        cpa(base + offB3, src3 + rk);
    };

    load_stage(0, 0);  cp_commit();
    load_stage(1, KC); cp_commit();

    const int KT = DIM / KC;
    int st = 0;
    for (int t = 0; t < KT; t++) {
        cp_wait1();
        __syncthreads();
        int nst = st + 2; if (nst >= 3) nst -= 3;
        if (t + 2 < KT) load_stage(nst, (t + 2) * KC);
        cp_commit();

        uint32_t base = sb + st * UP_STAGE;
        #pragma unroll
        for (int kk = 0; kk < KC; kk += 16) {
            uint32_t ah[2][4], al[2][4];
            #pragma unroll
            for (int mi = 0; mi < 2; mi++) {
                uint32_t ao = ((wm + mi * 16 + (lane & 15)) * APITCH + kk + ((lane >> 4) << 3)) * 2;
                ldsm_x4(ah[mi], base + ao);
                ldsm_x4(al[mi], base + A_ST * 2 + ao);
            }
            uint32_t b1[2][4], b3[2][4];
            #pragma unroll
            for (int g = 0; g < 2; g++) {
                uint32_t bo = ((kk + (lane & 15)) * BP_UP + wn + g * 16 + ((lane >> 4) << 3)) * 2;
                ldsm_x4t(b1[g], base + (2 * A_ST) * 2 + bo);
                ldsm_x4t(b3[g], base + (2 * A_ST + BU_ST) * 2 + bo);
            }
            #pragma unroll
            for (int ni = 0; ni < 4; ni++) {
                int g = ni >> 1, o = (ni & 1) * 2;
                #pragma unroll
                for (int mi = 0; mi < 2; mi++) {
                    mma16816(acc1[mi][ni], ah[mi], &b1[g][o]);
                    mma16816(acc1[mi][ni], al[mi], &b1[g][o]);
                    mma16816(acc3[mi][ni], ah[mi], &b3[g][o]);
                    mma16816(acc3[mi][ni], al[mi], &b3[g][o]);
                }
            }
        }
        __syncthreads();
        if (++st == 3) st = 0;
    }

    #pragma unroll
    for (int mi = 0; mi < 2; mi++)
        #pragma unroll
        for (int half = 0; half < 2; half++) {
            int r = m0 + wm + mi * 16 + (lane >> 2) + half * 8;
            if (r >= M) continue;
            size_t orow = ROUTED ? (size_t)g_entries[e * NT + r] : (size_t)r;
            #pragma unroll
            for (int ni = 0; ni < 4; ni++) {
                float v1a = acc1[mi][ni][half * 2 + 0], v1b = acc1[mi][ni][half * 2 + 1];
                float v3a = acc3[mi][ni][half * 2 + 0], v3b = acc3[mi][ni][half * 2 + 1];
                float oa, ob;
                if (ROUTED) {
                    float pa = v1a * v3a, pb = v1b * v3b;
                    oa = pa * sigmoidf_(pa);
                    ob = pb * sigmoidf_(pb);
                } else {
                    oa = v1a * sigmoidf_(v1a) * v3a;
                    ob = v1b * sigmoidf_(v1b) * v3b;
                }
                __half2 h2 = __floats2half2_rn(oa, ob);
                *(__half2*)&O[orow * HID + n0 + wn + ni * 8 + ((lane & 3) << 1)] = h2;
            }
        }
}

// ================ down: Y = H @ W2, tile 128(M) x 128(N), single-plane A ========
template<bool ROUTED>
__global__ __launch_bounds__(256, 2) void down_k(
        const fp16* __restrict__ H, const fp16* __restrict__ W2,
        float* __restrict__ out)
{
    int e  = ROUTED ? blockIdx.z : 0;
    int M  = ROUTED ? g_counts[e] : NT;
    int m0 = blockIdx.x * 128;
    if (m0 >= M) return;
    int n0 = blockIdx.y * 128;
    size_t woff = ROUTED ? (size_t)e * HID * DIM : 0;
    const fp16* w2 = W2 + woff;

    extern __shared__ char smem[];
    int tid = threadIdx.x, lane = tid & 31, warp = tid >> 5;
    int wm = (warp & 1) * 64, wn = (warp >> 1) * 32;

    int ar = tid >> 1, ac = (tid & 1) * 16;
    int gr = m0 + ar; if (gr >= M) gr = m0;
    size_t rid = ROUTED ? (size_t)g_entries[e * NT + gr] : (size_t)gr;
    const fp16* srcA = H + rid * HID + ac;

    int br = tid >> 3, bc = (tid & 7) * 16;
    const fp16* srcB = w2 + (size_t)br * DIM + n0 + bc;

    uint32_t sb = saddr(smem);
    uint32_t offA = (uint32_t)(ar * APITCH + ac) * 2;
    uint32_t offB = (A_ST + br * BP_DN + bc) * 2;

    float acc[4][4][4] = {};

    auto load_stage = [&](int st, int k0) {
        uint32_t base = sb + st * DOWN_STAGE;
        cpa(base + offA,      srcA + k0);
        cpa(base + offA + 16, srcA + k0 + 8);
        size_t rk = (size_t)k0 * DIM;
        cpa(base + offB,      srcB + rk);
        cpa(base + offB + 16, srcB + rk + 8);
    };

    load_stage(0, 0);      cp_commit();
    load_stage(1, KC);     cp_commit();
    load_stage(2, 2 * KC); cp_commit();

    const int KT = HID / KC;
    for (int t = 0; t < KT; t++) {
        int st = t & 3;
        cp_wait2();
        __syncthreads();
        if (t + 3 < KT) load_stage((t + 3) & 3, (t + 3) * KC);
        cp_commit();

        uint32_t base = sb + st * DOWN_STAGE;
        #pragma unroll
        for (int kk = 0; kk < KC; kk += 16) {
            uint32_t ah[4][4];
            #pragma unroll
            for (int mi = 0; mi < 4; mi++) {
                uint32_t ao = ((wm + mi * 16 + (lane & 15)) * APITCH + kk + ((lane >> 4) << 3)) * 2;
                ldsm_x4(ah[mi], base + ao);
            }
            uint32_t bh[2][4];
            #pragma unroll
            for (int g = 0; g < 2; g++) {
                uint32_t bo = ((kk + (lane & 15)) * BP_DN + wn + g * 16 + ((lane >> 4) << 3)) * 2;
                ldsm_x4t(bh[g], base + A_ST * 2 + bo);
            }
            #pragma unroll
            for (int ni = 0; ni < 4; ni++) {
                int g = ni >> 1, o = (ni & 1) * 2;
                #pragma unroll
                for (int mi = 0; mi < 4; mi++)
                    mma16816(acc[mi][ni], ah[mi], &bh[g][o]);
            }
        }
        __syncthreads();
    }

    #pragma unroll
    for (int mi = 0; mi < 4; mi++)
        #pragma unroll
        for (int half = 0; half < 2; half++) {
            int r = m0 + wm + mi * 16 + (lane >> 2) + half * 8;
            if (r >= M) continue;
            if (ROUTED) {
                int slot = g_entries[e * NT + r];
                int tok  = slot >> 2;
                float w  = g_slotw[slot];
                #pragma unroll
                for (int ni = 0; ni < 4; ni++) {
                    int col = n0 + wn + ni * 8 + ((lane & 3) << 1);
                    atomicAdd(&out[(size_t)tok * DIM + col],     acc[mi][ni][half * 2 + 0] * w);
                    atomicAdd(&out[(size_t)tok * DIM + col + 1], acc[mi][ni][half * 2 + 1] * w);
                }
            } else {
                #pragma unroll
                for (int ni = 0; ni < 4; ni++) {
                    float2 o;
                    o.x = acc[mi][ni][half * 2 + 0];
                    o.y = acc[mi][ni][half * 2 + 1];
                    *(float2*)&out[(size_t)r * DIM + n0 + wn + ni * 8 + ((lane & 3) << 1)] = o;
                }
            }
        }
}

static void* sym(const void* s) { void* p; cudaGetSymbolAddress(&p, s); return p; }

extern "C" void kernel_launch(void* const* d_in, const int* in_sizes, int n_in,
                              void* d_out, int out_size)
{
    (void)in_sizes; (void)n_in; (void)out_size;
    const float* x   = (const float*)d_in[0];
    const float* gw  = (const float*)d_in[1];
    const float* gb  = (const float*)d_in[2];
    const float* w1s = (const float*)d_in[3];
    const float* w2s = (const float*)d_in[4];
    const float* w3s = (const float*)d_in[5];
    const float* w1r = (const float*)d_in[6];
    const float* w2r = (const float*)d_in[7];
    const float* w3r = (const float*)d_in[8];
    float* out = (float*)d_out;

    fp16 *xh = (fp16*)sym(g_xh), *xl = (fp16*)sym(g_xl);
    fp16 *pw1s = (fp16*)sym(g_w1s), *pw3s = (fp16*)sym(g_w3s), *pw2s = (fp16*)sym(g_w2s);
    fp16 *pw1r = (fp16*)sym(g_w1r), *pw3r = (fp16*)sym(g_w3r), *pw2r = (fp16*)sym(g_w2r);
    fp16 *Hs = (fp16*)sym(g_Hs), *Hr = (fp16*)sym(g_Hr);

    cudaFuncSetAttribute(up_k<false>,  cudaFuncAttributeMaxDynamicSharedMemorySize, UP_SMEM);
    cudaFuncSetAttribute(up_k<true>,   cudaFuncAttributeMaxDynamicSharedMemorySize, UP_SMEM);
    cudaFuncSetAttribute(down_k<false>, cudaFuncAttributeMaxDynamicSharedMemorySize, DOWN_SMEM);
    cudaFuncSetAttribute(down_k<true>,  cudaFuncAttributeMaxDynamicSharedMemorySize, DOWN_SMEM);

    // All sizes are multiples of 8192 floats -> n4 % 2048 == 0; each thread does 8.
    auto cvt = [&](const float* s, fp16* d, size_t n) {
        int n4 = (int)(n / 4);
        int blocks = n4 / (256 * 8);
        cvt_kernel<<<blocks, 256>>>((const float4*)s, (uint2*)d);
    };

    zero_counts_kernel<<<1, 32>>>();
    gate_kernel<<<NT, 256>>>(x, gw, gb);

    {
        int n4 = (int)((size_t)NT * DIM / 4);
        split_kernel<<<n4 / (256 * 8), 256>>>((const float4*)x, (uint2*)xh, (uint2*)xl);
    }
    cvt(w1s, pw1s, (size_t)DIM * HID);
    cvt(w3s, pw3s, (size_t)DIM * HID);
    cvt(w2s, pw2s, (size_t)HID * DIM);
    cvt(w1r, pw1r, (size_t)NE * DIM * HID);
    cvt(w3r, pw3r, (size_t)NE * DIM * HID);
    cvt(w2r, pw2r, (size_t)NE * HID * DIM);

    // shared expert
    up_k<false><<<dim3(NT / 128, HID / 64), 256, UP_SMEM>>>(xh, xl, pw1s, pw3s, Hs);
    down_k<false><<<dim3(NT / 128, DIM / 128), 256, DOWN_SMEM>>>(Hs, pw2s, out);

    // routed experts
    up_k<true><<<dim3(NT / 128, HID / 64, NE), 256, UP_SMEM>>>(xh, xl, pw1r, pw3r, Hr);
    down_k<true><<<dim3(NT / 128, DIM / 128, NE), 256, DOWN_SMEM>>>(Hr, pw2r, out);
}

// round 9
// speedup vs baseline: 4.2123x; 1.0585x over previous
#include <cuda_runtime.h>
#include <cuda_fp16.h>
#include <math.h>
#include <stdint.h>

#define NT   2048
#define DIM  2048
#define HID  1408
#define NE   16
#define TOPK 4
#define KC   32

typedef __half fp16;

// ---- routing scratch ----
__device__ int   g_counts[NE];
__device__ int   g_entries[NE * NT];
__device__ float g_slotw[NT * TOPK];

// ---- fp16 planes (activations only; weights stay fp32 in-place) ----
__device__ fp16 g_xh[NT * DIM], g_xl[NT * DIM];
__device__ fp16 g_Hs[(size_t)NT * HID];
__device__ fp16 g_Hr[(size_t)NT * TOPK * HID];

__global__ void zero_counts_kernel() {
    if (threadIdx.x < NE) g_counts[threadIdx.x] = 0;
}

__device__ __forceinline__ uint32_t h2u(float a, float b) {
    __half2 h = __floats2half2_rn(a, b);
    return *(uint32_t*)&h;
}

// ---- fp32 -> fp16 hi/lo split (x): warp-interleaved, MLP 8 ----
__global__ __launch_bounds__(256) void split_kernel(const float4* __restrict__ src,
                                                    uint2* __restrict__ hi,
                                                    uint2* __restrict__ lo)
{
    int stride = gridDim.x * blockDim.x;
    int i = blockIdx.x * blockDim.x + threadIdx.x;
    float4 v[8];
    #pragma unroll
    for (int j = 0; j < 8; j++) v[j] = __ldcs(src + i + j * stride);
    #pragma unroll
    for (int j = 0; j < 8; j++) {
        float f[4] = { v[j].x, v[j].y, v[j].z, v[j].w };
        float h[4], l[4];
        #pragma unroll
        for (int q = 0; q < 4; q++) {
            h[q] = __half2float(__float2half_rn(f[q]));
            l[q] = f[q] - h[q];
        }
        uint2 oh, ol;
        oh.x = h2u(h[0], h[1]); oh.y = h2u(h[2], h[3]);
        ol.x = h2u(l[0], l[1]); ol.y = h2u(l[2], l[3]);
        __stcs(hi + i + j * stride, oh);
        __stcs(lo + i + j * stride, ol);
    }
}

// ---------------- gate ----------------
__global__ __launch_bounds__(256) void gate_kernel(const float* __restrict__ x,
                                                   const float* __restrict__ gw,
                                                   const float* __restrict__ gb)
{
    int t = blockIdx.x;
    __shared__ float xs[DIM];
    for (int i = threadIdx.x; i < DIM; i += blockDim.x)
        xs[i] = x[(size_t)t * DIM + i];
    __syncthreads();

    __shared__ float logits[NE];
    int warp = threadIdx.x >> 5, lane = threadIdx.x & 31;
    for (int e = warp; e < NE; e += 8) {
        const float* w = gw + (size_t)e * DIM;
        float s = 0.f;
        for (int d = lane; d < DIM; d += 32) s += w[d] * xs[d];
        #pragma unroll
        for (int o = 16; o > 0; o >>= 1) s += __shfl_down_sync(0xffffffffu, s, o);
        if (lane == 0) logits[e] = s;
    }
    __syncthreads();

    if (threadIdx.x == 0) {
        float sc[NE];
        #pragma unroll
        for (int e = 0; e < NE; e++)
            sc[e] = 1.f / (1.f + expf(-logits[e])) + gb[e];
        int idx[TOPK]; float wv[TOPK]; float sum = 0.f;
        bool used[NE];
        #pragma unroll
        for (int e = 0; e < NE; e++) used[e] = false;
        #pragma unroll
        for (int k = 0; k < TOPK; k++) {
            float best = -1e30f; int bi = 0;
            #pragma unroll
            for (int e = 0; e < NE; e++)
                if (!used[e] && sc[e] > best) { best = sc[e]; bi = e; }
            used[bi] = true; idx[k] = bi; wv[k] = best; sum += best;
        }
        float inv = 1.f / sum;
        #pragma unroll
        for (int k = 0; k < TOPK; k++) {
            int e = idx[k];
            int pos = atomicAdd(&g_counts[e], 1);
            g_entries[e * NT + pos] = t * TOPK + k;
            g_slotw[t * TOPK + k]   = wv[k] * inv;
        }
    }
}

__device__ __forceinline__ float sigmoidf_(float v) { return 1.f / (1.f + expf(-v)); }

// ---------------- asm helpers ----------------
__device__ __forceinline__ uint32_t saddr(const void* p) {
    return (uint32_t)__cvta_generic_to_shared(p);
}
__device__ __forceinline__ void cpa(uint32_t dst, const void* src) {
    asm volatile("cp.async.cg.shared.global [%0], [%1], 16;" :: "r"(dst), "l"(src));
}
__device__ __forceinline__ void cp_commit() { asm volatile("cp.async.commit_group;"); }
__device__ __forceinline__ void cp_wait1()  { asm volatile("cp.async.wait_group 1;"); }
__device__ __forceinline__ void cp_wait2()  { asm volatile("cp.async.wait_group 2;"); }
__device__ __forceinline__ void ldsm_x4(uint32_t r[4], uint32_t a) {
    asm volatile("ldmatrix.sync.aligned.m8n8.x4.shared.b16 {%0,%1,%2,%3}, [%4];"
                 : "=r"(r[0]), "=r"(r[1]), "=r"(r[2]), "=r"(r[3]) : "r"(a));
}
__device__ __forceinline__ void ldsm_x4t(uint32_t r[4], uint32_t a) {
    asm volatile("ldmatrix.sync.aligned.m8n8.x4.trans.shared.b16 {%0,%1,%2,%3}, [%4];"
                 : "=r"(r[0]), "=r"(r[1]), "=r"(r[2]), "=r"(r[3]) : "r"(a));
}
__device__ __forceinline__ void mma16816(float c[4], const uint32_t a[4], const uint32_t b[2]) {
    asm volatile("mma.sync.aligned.m16n8k16.row.col.f32.f16.f16.f32 "
                 "{%0,%1,%2,%3}, {%4,%5,%6,%7}, {%8,%9}, {%0,%1,%2,%3};"
                 : "+f"(c[0]), "+f"(c[1]), "+f"(c[2]), "+f"(c[3])
                 : "r"(a[0]), "r"(a[1]), "r"(a[2]), "r"(a[3]), "r"(b[0]), "r"(b[1]));
}

#define APITCH 40
#define BP_UP  72
#define BP_DN  136
#define A_ST   (128 * APITCH)
#define BU_ST  (32 * BP_UP)
#define BD_ST  (32 * BP_DN)
#define UP_STAGE   ((2 * A_ST + 2 * BU_ST) * 2)
#define DOWN_STAGE ((A_ST + BD_ST) * 2)
#define UP_SMEM    (3 * UP_STAGE)     // 89 KB -> 2 CTAs/SM
#define DOWN_SMEM  (4 * DOWN_STAGE)   // 75.8 KB -> 2 CTAs/SM

// ================ up: H = f(X@W1, X@W3), tile 128(M) x 64(H cols) ================
// A (x hi/lo fp16) via cp.async ring; B (fp32 weights) via LDG->cvt->STS pipeline.
template<bool ROUTED>
__global__ __launch_bounds__(256, 2) void up_k(
        const fp16* __restrict__ Xh, const fp16* __restrict__ Xl,
        const float* __restrict__ W1, const float* __restrict__ W3,
        fp16* __restrict__ O)
{
    int e  = ROUTED ? blockIdx.z : 0;
    int M  = ROUTED ? g_counts[e] : NT;
    int m0 = blockIdx.x * 128;
    if (m0 >= M) return;
    int n0 = blockIdx.y * 64;
    size_t woff = ROUTED ? (size_t)e * DIM * HID : 0;
    const float* w1 = W1 + woff;
    const float* w3 = W3 + woff;

    extern __shared__ char smem[];
    int tid = threadIdx.x, lane = tid & 31, warp = tid >> 5;
    int wm = (warp & 3) * 32, wn = (warp >> 2) * 32;

    int ar = tid >> 1, ac = (tid & 1) * 16;
    int gr = m0 + ar; if (gr >= M) gr = m0;
    int tok = ROUTED ? (g_entries[e * NT + gr] >> 2) : gr;
    const fp16* srcAh = Xh + (size_t)tok * DIM + ac;
    const fp16* srcAl = Xl + (size_t)tok * DIM + ac;

    int br = tid >> 3, bc = (tid & 7) * 8;     // B: row br (k), 8 cols
    const float* src1 = w1 + (size_t)br * HID + n0 + bc;
    const float* src3 = w3 + (size_t)br * HID + n0 + bc;

    uint32_t sb = saddr(smem);
    uint32_t offAh = (uint32_t)(ar * APITCH + ac) * 2;
    uint32_t offAl = offAh + A_ST * 2;
    uint32_t offB1 = (2 * A_ST + br * BP_UP + bc) * 2;   // byte offsets in stage
    uint32_t offB3 = offB1 + BU_ST * 2;

    float acc1[2][4][4] = {}, acc3[2][4][4] = {};
    float4 b1v[2], b3v[2];

    auto loadA = [&](int st, int k0) {
        uint32_t base = sb + st * UP_STAGE;
        cpa(base + offAh,      srcAh + k0);
        cpa(base + offAh + 16, srcAh + k0 + 8);
        cpa(base + offAl,      srcAl + k0);
        cpa(base + offAl + 16, srcAl + k0 + 8);
    };
    auto ldgB = [&](int k0) {
        const float4* p1 = (const float4*)(src1 + (size_t)k0 * HID);
        const float4* p3 = (const float4*)(src3 + (size_t)k0 * HID);
        b1v[0] = __ldg(p1); b1v[1] = __ldg(p1 + 1);
        b3v[0] = __ldg(p3); b3v[1] = __ldg(p3 + 1);
    };
    auto stsB = [&](int st) {
        char* base = smem + st * UP_STAGE;
        uint4 o1, o3;
        o1.x = h2u(b1v[0].x, b1v[0].y); o1.y = h2u(b1v[0].z, b1v[0].w);
        o1.z = h2u(b1v[1].x, b1v[1].y); o1.w = h2u(b1v[1].z, b1v[1].w);
        o3.x = h2u(b3v[0].x, b3v[0].y); o3.y = h2u(b3v[0].z, b3v[0].w);
        o3.z = h2u(b3v[1].x, b3v[1].y); o3.w = h2u(b3v[1].z, b3v[1].w);
        *(uint4*)(base + offB1) = o1;
        *(uint4*)(base + offB3) = o3;
    };

    // prologue
    ldgB(0);  stsB(0);  ldgB(KC);
    loadA(0, 0);  cp_commit();
    loadA(1, KC); cp_commit();

    const int KT = DIM / KC;
    int st = 0;
    for (int t = 0; t < KT; t++) {
        cp_wait1();
        __syncthreads();
        int st1 = st + 1; if (st1 == 3) st1 = 0;
        int st2 = st1 + 1; if (st2 == 3) st2 = 0;
        if (t + 1 < KT) stsB(st1);               // B_{t+1} regs -> smem
        if (t + 2 < KT) ldgB((t + 2) * KC);      // B_{t+2} -> regs
        if (t + 2 < KT) loadA(st2, (t + 2) * KC);
        cp_commit();

        uint32_t base = sb + st * UP_STAGE;
        #pragma unroll
        for (int kk = 0; kk < KC; kk += 16) {
            uint32_t ah[2][4], al[2][4];
            #pragma unroll
            for (int mi = 0; mi < 2; mi++) {
                uint32_t ao = ((wm + mi * 16 + (lane & 15)) * APITCH + kk + ((lane >> 4) << 3)) * 2;
                ldsm_x4(ah[mi], base + ao);
                ldsm_x4(al[mi], base + A_ST * 2 + ao);
            }
            uint32_t b1[2][4], b3[2][4];
            #pragma unroll
            for (int g = 0; g < 2; g++) {
                uint32_t bo = ((kk + (lane & 15)) * BP_UP + wn + g * 16 + ((lane >> 4) << 3)) * 2;
                ldsm_x4t(b1[g], base + (2 * A_ST) * 2 + bo);
                ldsm_x4t(b3[g], base + (2 * A_ST + BU_ST) * 2 + bo);
            }
            #pragma unroll
            for (int ni = 0; ni < 4; ni++) {
                int g = ni >> 1, o = (ni & 1) * 2;
                #pragma unroll
                for (int mi = 0; mi < 2; mi++) {
                    mma16816(acc1[mi][ni], ah[mi], &b1[g][o]);
                    mma16816(acc1[mi][ni], al[mi], &b1[g][o]);
                    mma16816(acc3[mi][ni], ah[mi], &b3[g][o]);
                    mma16816(acc3[mi][ni], al[mi], &b3[g][o]);
                }
            }
        }
        __syncthreads();
        if (++st == 3) st = 0;
    }

    #pragma unroll
    for (int mi = 0; mi < 2; mi++)
        #pragma unroll
        for (int half = 0; half < 2; half++) {
            int r = m0 + wm + mi * 16 + (lane >> 2) + half * 8;
            if (r >= M) continue;
            size_t orow = ROUTED ? (size_t)g_entries[e * NT + r] : (size_t)r;
            #pragma unroll
            for (int ni = 0; ni < 4; ni++) {
                float v1a = acc1[mi][ni][half * 2 + 0], v1b = acc1[mi][ni][half * 2 + 1];
                float v3a = acc3[mi][ni][half * 2 + 0], v3b = acc3[mi][ni][half * 2 + 1];
                float oa, ob;
                if (ROUTED) {
                    float pa = v1a * v3a, pb = v1b * v3b;
                    oa = pa * sigmoidf_(pa);
                    ob = pb * sigmoidf_(pb);
                } else {
                    oa = v1a * sigmoidf_(v1a) * v3a;
                    ob = v1b * sigmoidf_(v1b) * v3b;
                }
                __half2 h2 = __floats2half2_rn(oa, ob);
                *(__half2*)&O[orow * HID + n0 + wn + ni * 8 + ((lane & 3) << 1)] = h2;
            }
        }
}

// ================ down: Y = H @ W2, tile 128(M) x 128(N) =========================
template<bool ROUTED>
__global__ __launch_bounds__(256, 2) void down_k(
        const fp16* __restrict__ H, const float* __restrict__ W2,
        float* __restrict__ out)
{
    int e  = ROUTED ? blockIdx.z : 0;
    int M  = ROUTED ? g_counts[e] : NT;
    int m0 = blockIdx.x * 128;
    if (m0 >= M) return;
    int n0 = blockIdx.y * 128;
    size_t woff = ROUTED ? (size_t)e * HID * DIM : 0;
    const float* w2 = W2 + woff;

    extern __shared__ char smem[];
    int tid = threadIdx.x, lane = tid & 31, warp = tid >> 5;
    int wm = (warp & 1) * 64, wn = (warp >> 1) * 32;

    int ar = tid >> 1, ac = (tid & 1) * 16;
    int gr = m0 + ar; if (gr >= M) gr = m0;
    size_t rid = ROUTED ? (size_t)g_entries[e * NT + gr] : (size_t)gr;
    const fp16* srcA = H + rid * HID + ac;

    int br = tid >> 3, bc = (tid & 7) * 16;    // B: row br, 16 cols fp32
    const float* srcB = w2 + (size_t)br * DIM + n0 + bc;

    uint32_t sb = saddr(smem);
    uint32_t offA = (uint32_t)(ar * APITCH + ac) * 2;
    uint32_t offB = (A_ST + br * BP_DN + bc) * 2;

    float acc[4][4][4] = {};
    float4 bv[4];

    auto loadA = [&](int st, int k0) {
        uint32_t base = sb + st * DOWN_STAGE;
        cpa(base + offA,      srcA + k0);
        cpa(base + offA + 16, srcA + k0 + 8);
    };
    auto ldgB = [&](int k0) {
        const float4* p = (const float4*)(srcB + (size_t)k0 * DIM);
        bv[0] = __ldg(p);     bv[1] = __ldg(p + 1);
        bv[2] = __ldg(p + 2); bv[3] = __ldg(p + 3);
    };
    auto stsB = [&](int st) {
        char* base = smem + st * DOWN_STAGE;
        uint4 o0, o1;
        o0.x = h2u(bv[0].x, bv[0].y); o0.y = h2u(bv[0].z, bv[0].w);
        o0.z = h2u(bv[1].x, bv[1].y); o0.w = h2u(bv[1].z, bv[1].w);
        o1.x = h2u(bv[2].x, bv[2].y); o1.y = h2u(bv[2].z, bv[2].w);
        o1.z = h2u(bv[3].x, bv[3].y); o1.w = h2u(bv[3].z, bv[3].w);
        *(uint4*)(base + offB)      = o0;
        *(uint4*)(base + offB + 16) = o1;
    };

    // prologue
    ldgB(0);  stsB(0);  ldgB(KC);
    loadA(0, 0);      cp_commit();
    loadA(1, KC);     cp_commit();
    loadA(2, 2 * KC); cp_commit();

    const int KT = HID / KC;
    for (int t = 0; t < KT; t++) {
        int st = t & 3;
        cp_wait2();
        __syncthreads();
        if (t + 1 < KT) stsB((t + 1) & 3);
        if (t + 2 < KT) ldgB((t + 2) * KC);
        if (t + 3 < KT) loadA((t + 3) & 3, (t + 3) * KC);
        cp_commit();

        uint32_t base = sb + st * DOWN_STAGE;
        #pragma unroll
        for (int kk = 0; kk < KC; kk += 16) {
            uint32_t ah[4][4];
            #pragma unroll
            for (int mi = 0; mi < 4; mi++) {
                uint32_t ao = ((wm + mi * 16 + (lane & 15)) * APITCH + kk + ((lane >> 4) << 3)) * 2;
                ldsm_x4(ah[mi], base + ao);
            }
            uint32_t bh[2][4];
            #pragma unroll
            for (int g = 0; g < 2; g++) {
                uint32_t bo = ((kk + (lane & 15)) * BP_DN + wn + g * 16 + ((lane >> 4) << 3)) * 2;
                ldsm_x4t(bh[g], base + A_ST * 2 + bo);
            }
            #pragma unroll
            for (int ni = 0; ni < 4; ni++) {
                int g = ni >> 1, o = (ni & 1) * 2;
                #pragma unroll
                for (int mi = 0; mi < 4; mi++)
                    mma16816(acc[mi][ni], ah[mi], &bh[g][o]);
            }
        }
        __syncthreads();
    }

    #pragma unroll
    for (int mi = 0; mi < 4; mi++)
        #pragma unroll
        for (int half = 0; half < 2; half++) {
            int r = m0 + wm + mi * 16 + (lane >> 2) + half * 8;
            if (r >= M) continue;
            if (ROUTED) {
                int slot = g_entries[e * NT + r];
                int tok  = slot >> 2;
                float w  = g_slotw[slot];
                #pragma unroll
                for (int ni = 0; ni < 4; ni++) {
                    int col = n0 + wn + ni * 8 + ((lane & 3) << 1);
                    atomicAdd(&out[(size_t)tok * DIM + col],     acc[mi][ni][half * 2 + 0] * w);
                    atomicAdd(&out[(size_t)tok * DIM + col + 1], acc[mi][ni][half * 2 + 1] * w);
                }
            } else {
                #pragma unroll
                for (int ni = 0; ni < 4; ni++) {
                    float2 o;
                    o.x = acc[mi][ni][half * 2 + 0];
                    o.y = acc[mi][ni][half * 2 + 1];
                    *(float2*)&out[(size_t)r * DIM + n0 + wn + ni * 8 + ((lane & 3) << 1)] = o;
                }
            }
        }
}

static void* sym(const void* s) { void* p; cudaGetSymbolAddress(&p, s); return p; }

extern "C" void kernel_launch(void* const* d_in, const int* in_sizes, int n_in,
                              void* d_out, int out_size)
{
    (void)in_sizes; (void)n_in; (void)out_size;
    const float* x   = (const float*)d_in[0];
    const float* gw  = (const float*)d_in[1];
    const float* gb  = (const float*)d_in[2];
    const float* w1s = (const float*)d_in[3];
    const float* w2s = (const float*)d_in[4];
    const float* w3s = (const float*)d_in[5];
    const float* w1r = (const float*)d_in[6];
    const float* w2r = (const float*)d_in[7];
    const float* w3r = (const float*)d_in[8];
    float* out = (float*)d_out;

    fp16 *xh = (fp16*)sym(g_xh), *xl = (fp16*)sym(g_xl);
    fp16 *Hs = (fp16*)sym(g_Hs), *Hr = (fp16*)sym(g_Hr);

    cudaFuncSetAttribute(up_k<false>,  cudaFuncAttributeMaxDynamicSharedMemorySize, UP_SMEM);
    cudaFuncSetAttribute(up_k<true>,   cudaFuncAttributeMaxDynamicSharedMemorySize, UP_SMEM);
    cudaFuncSetAttribute(down_k<false>, cudaFuncAttributeMaxDynamicSharedMemorySize, DOWN_SMEM);
    cudaFuncSetAttribute(down_k<true>,  cudaFuncAttributeMaxDynamicSharedMemorySize, DOWN_SMEM);

    zero_counts_kernel<<<1, 32>>>();
    gate_kernel<<<NT, 256>>>(x, gw, gb);

    {
        int n4 = (int)((size_t)NT * DIM / 4);
        split_kernel<<<n4 / (256 * 8), 256>>>((const float4*)x, (uint2*)xh, (uint2*)xl);
    }

    // shared expert
    up_k<false><<<dim3(NT / 128, HID / 64), 256, UP_SMEM>>>(xh, xl, w1s, w3s, Hs);
    down_k<false><<<dim3(NT / 128, DIM / 128), 256, DOWN_SMEM>>>(Hs, w2s, out);

    // routed experts
    up_k<true><<<dim3(NT / 128, HID / 64, NE), 256, UP_SMEM>>>(xh, xl, w1r, w3r, Hr);
    down_k<true><<<dim3(NT / 128, DIM / 128, NE), 256, DOWN_SMEM>>>(Hr, w2r, out);
}

// round 10
// speedup vs baseline: 5.5650x; 1.3211x over previous
#include <cuda_runtime.h>
#include <cuda_fp16.h>
#include <math.h>
#include <stdint.h>

#define NT   2048
#define DIM  2048
#define HID  1408
#define NE   16
#define TOPK 4
#define KC   32

typedef __half fp16;

// ---- routing scratch ----
__device__ int   g_counts[NE];
__device__ int   g_entries[NE * NT];
__device__ float g_slotw[NT * TOPK];

// ---- fp16 activations (weights stay fp32, converted in-GEMM) ----
__device__ fp16 g_x16[NT * DIM];
__device__ fp16 g_Hs[(size_t)NT * HID];
__device__ fp16 g_Hr[(size_t)NT * TOPK * HID];

__global__ void zero_counts_kernel() {
    if (threadIdx.x < NE) g_counts[threadIdx.x] = 0;
}

__device__ __forceinline__ uint32_t h2u(float a, float b) {
    __half2 h = __floats2half2_rn(a, b);
    return *(uint32_t*)&h;
}

// ---- fp32 -> fp16 convert (x): warp-interleaved, MLP 8 ----
__global__ __launch_bounds__(256) void cvtx_kernel(const float4* __restrict__ src,
                                                   uint2* __restrict__ dst)
{
    int stride = gridDim.x * blockDim.x;
    int i = blockIdx.x * blockDim.x + threadIdx.x;
    float4 v[8];
    #pragma unroll
    for (int j = 0; j < 8; j++) v[j] = __ldcs(src + i + j * stride);
    #pragma unroll
    for (int j = 0; j < 8; j++) {
        uint2 o;
        o.x = h2u(v[j].x, v[j].y);
        o.y = h2u(v[j].z, v[j].w);
        __stcs(dst + i + j * stride, o);
    }
}

// ---------------- gate ----------------
__global__ __launch_bounds__(256) void gate_kernel(const float* __restrict__ x,
                                                   const float* __restrict__ gw,
                                                   const float* __restrict__ gb)
{
    int t = blockIdx.x;
    __shared__ float xs[DIM];
    for (int i = threadIdx.x; i < DIM; i += blockDim.x)
        xs[i] = x[(size_t)t * DIM + i];
    __syncthreads();

    __shared__ float logits[NE];
    int warp = threadIdx.x >> 5, lane = threadIdx.x & 31;
    for (int e = warp; e < NE; e += 8) {
        const float* w = gw + (size_t)e * DIM;
        float s = 0.f;
        for (int d = lane; d < DIM; d += 32) s += w[d] * xs[d];
        #pragma unroll
        for (int o = 16; o > 0; o >>= 1) s += __shfl_down_sync(0xffffffffu, s, o);
        if (lane == 0) logits[e] = s;
    }
    __syncthreads();

    if (threadIdx.x == 0) {
        float sc[NE];
        #pragma unroll
        for (int e = 0; e < NE; e++)
            sc[e] = 1.f / (1.f + expf(-logits[e])) + gb[e];
        int idx[TOPK]; float wv[TOPK]; float sum = 0.f;
        bool used[NE];
        #pragma unroll
        for (int e = 0; e < NE; e++) used[e] = false;
        #pragma unroll
        for (int k = 0; k < TOPK; k++) {
            float best = -1e30f; int bi = 0;
            #pragma unroll
            for (int e = 0; e < NE; e++)
                if (!used[e] && sc[e] > best) { best = sc[e]; bi = e; }
            used[bi] = true; idx[k] = bi; wv[k] = best; sum += best;
        }
        float inv = 1.f / sum;
        #pragma unroll
        for (int k = 0; k < TOPK; k++) {
            int e = idx[k];
            int pos = atomicAdd(&g_counts[e], 1);
            g_entries[e * NT + pos] = t * TOPK + k;
            g_slotw[t * TOPK + k]   = wv[k] * inv;
        }
    }
}

__device__ __forceinline__ float sigmoidf_(float v) { return 1.f / (1.f + expf(-v)); }

// ---------------- asm helpers ----------------
__device__ __forceinline__ uint32_t saddr(const void* p) {
    return (uint32_t)__cvta_generic_to_shared(p);
}
__device__ __forceinline__ void cpa(uint32_t dst, const void* src) {
    asm volatile("cp.async.cg.shared.global [%0], [%1], 16;" :: "r"(dst), "l"(src));
}
__device__ __forceinline__ void cp_commit() { asm volatile("cp.async.commit_group;"); }
__device__ __forceinline__ void cp_wait2()  { asm volatile("cp.async.wait_group 2;"); }
__device__ __forceinline__ void ldsm_x4(uint32_t r[4], uint32_t a) {
    asm volatile("ldmatrix.sync.aligned.m8n8.x4.shared.b16 {%0,%1,%2,%3}, [%4];"
                 : "=r"(r[0]), "=r"(r[1]), "=r"(r[2]), "=r"(r[3]) : "r"(a));
}
__device__ __forceinline__ void ldsm_x4t(uint32_t r[4], uint32_t a) {
    asm volatile("ldmatrix.sync.aligned.m8n8.x4.trans.shared.b16 {%0,%1,%2,%3}, [%4];"
                 : "=r"(r[0]), "=r"(r[1]), "=r"(r[2]), "=r"(r[3]) : "r"(a));
}
__device__ __forceinline__ void mma16816(float c[4], const uint32_t a[4], const uint32_t b[2]) {
    asm volatile("mma.sync.aligned.m16n8k16.row.col.f32.f16.f16.f32 "
                 "{%0,%1,%2,%3}, {%4,%5,%6,%7}, {%8,%9}, {%0,%1,%2,%3};"
                 : "+f"(c[0]), "+f"(c[1]), "+f"(c[2]), "+f"(c[3])
                 : "r"(a[0]), "r"(a[1]), "r"(a[2]), "r"(a[3]), "r"(b[0]), "r"(b[1]));
}

#define APITCH 40
#define BP_UP  72
#define BP_DN  136
#define A_ST   (128 * APITCH)
#define BU_ST  (32 * BP_UP)
#define BD_ST  (32 * BP_DN)
#define UP_STAGE   ((A_ST + 2 * BU_ST) * 2)   // A single, B1, B3 : 19456 B
#define DOWN_STAGE ((A_ST + BD_ST) * 2)       // 18944 B
#define UP_SMEM    (4 * UP_STAGE)             // 77.8 KB -> 2 CTAs/SM
#define DOWN_SMEM  (4 * DOWN_STAGE)           // 75.8 KB -> 2 CTAs/SM

// ================ up: H = f(X@W1, X@W3), tile 128(M) x 64(H cols) ================
template<bool ROUTED>
__global__ __launch_bounds__(256, 2) void up_k(
        const fp16* __restrict__ X,
        const float* __restrict__ W1, const float* __restrict__ W3,
        fp16* __restrict__ O)
{
    int e  = ROUTED ? blockIdx.z : 0;
    int M  = ROUTED ? g_counts[e] : NT;
    int m0 = blockIdx.x * 128;
    if (m0 >= M) return;
    int n0 = blockIdx.y * 64;
    size_t woff = ROUTED ? (size_t)e * DIM * HID : 0;
    const float* w1 = W1 + woff;
    const float* w3 = W3 + woff;

    extern __shared__ char smem[];
    int tid = threadIdx.x, lane = tid & 31, warp = tid >> 5;
    int wm = (warp & 3) * 32, wn = (warp >> 2) * 32;

    int ar = tid >> 1, ac = (tid & 1) * 16;
    int gr = m0 + ar; if (gr >= M) gr = m0;
    int tok = ROUTED ? (g_entries[e * NT + gr] >> 2) : gr;
    const fp16* srcA = X + (size_t)tok * DIM + ac;

    int br = tid >> 3, bc = (tid & 7) * 8;
    const float* src1 = w1 + (size_t)br * HID + n0 + bc;
    const float* src3 = w3 + (size_t)br * HID + n0 + bc;

    uint32_t sb = saddr(smem);
    uint32_t offA  = (uint32_t)(ar * APITCH + ac) * 2;
    uint32_t offB1 = (A_ST + br * BP_UP + bc) * 2;
    uint32_t offB3 = offB1 + BU_ST * 2;

    float acc1[2][4][4] = {}, acc3[2][4][4] = {};
    float4 b1v[2], b3v[2];

    auto loadA = [&](int st, int k0) {
        uint32_t base = sb + st * UP_STAGE;
        cpa(base + offA,      srcA + k0);
        cpa(base + offA + 16, srcA + k0 + 8);
    };
    auto ldgB = [&](int k0) {
        const float4* p1 = (const float4*)(src1 + (size_t)k0 * HID);
        const float4* p3 = (const float4*)(src3 + (size_t)k0 * HID);
        b1v[0] = __ldg(p1); b1v[1] = __ldg(p1 + 1);
        b3v[0] = __ldg(p3); b3v[1] = __ldg(p3 + 1);
    };
    auto stsB = [&](int st) {
        char* base = smem + st * UP_STAGE;
        uint4 o1, o3;
        o1.x = h2u(b1v[0].x, b1v[0].y); o1.y = h2u(b1v[0].z, b1v[0].w);
        o1.z = h2u(b1v[1].x, b1v[1].y); o1.w = h2u(b1v[1].z, b1v[1].w);
        o3.x = h2u(b3v[0].x, b3v[0].y); o3.y = h2u(b3v[0].z, b3v[0].w);
        o3.z = h2u(b3v[1].x, b3v[1].y); o3.w = h2u(b3v[1].z, b3v[1].w);
        *(uint4*)(base + offB1) = o1;
        *(uint4*)(base + offB3) = o3;
    };

    // prologue
    ldgB(0);  stsB(0);  ldgB(KC);
    loadA(0, 0);      cp_commit();
    loadA(1, KC);     cp_commit();
    loadA(2, 2 * KC); cp_commit();

    const int KT = DIM / KC;
    for (int t = 0; t < KT; t++) {
        int st = t & 3;
        cp_wait2();
        __syncthreads();
        if (t + 1 < KT) stsB((t + 1) & 3);
        if (t + 2 < KT) ldgB((t + 2) * KC);
        if (t + 3 < KT) loadA((t + 3) & 3, (t + 3) * KC);
        cp_commit();

        uint32_t base = sb + st * UP_STAGE;
        #pragma unroll
        for (int kk = 0; kk < KC; kk += 16) {
            uint32_t ah[2][4];
            #pragma unroll
            for (int mi = 0; mi < 2; mi++) {
                uint32_t ao = ((wm + mi * 16 + (lane & 15)) * APITCH + kk + ((lane >> 4) << 3)) * 2;
                ldsm_x4(ah[mi], base + ao);
            }
            uint32_t b1[2][4], b3[2][4];
            #pragma unroll
            for (int g = 0; g < 2; g++) {
                uint32_t bo = ((kk + (lane & 15)) * BP_UP + wn + g * 16 + ((lane >> 4) << 3)) * 2;
                ldsm_x4t(b1[g], base + A_ST * 2 + bo);
                ldsm_x4t(b3[g], base + (A_ST + BU_ST) * 2 + bo);
            }
            #pragma unroll
            for (int ni = 0; ni < 4; ni++) {
                int g = ni >> 1, o = (ni & 1) * 2;
                #pragma unroll
                for (int mi = 0; mi < 2; mi++) {
                    mma16816(acc1[mi][ni], ah[mi], &b1[g][o]);
                    mma16816(acc3[mi][ni], ah[mi], &b3[g][o]);
                }
            }
        }
        __syncthreads();
    }

    #pragma unroll
    for (int mi = 0; mi < 2; mi++)
        #pragma unroll
        for (int half = 0; half < 2; half++) {
            int r = m0 + wm + mi * 16 + (lane >> 2) + half * 8;
            if (r >= M) continue;
            size_t orow = ROUTED ? (size_t)g_entries[e * NT + r] : (size_t)r;
            #pragma unroll
            for (int ni = 0; ni < 4; ni++) {
                float v1a = acc1[mi][ni][half * 2 + 0], v1b = acc1[mi][ni][half * 2 + 1];
                float v3a = acc3[mi][ni][half * 2 + 0], v3b = acc3[mi][ni][half * 2 + 1];
                float oa, ob;
                if (ROUTED) {
                    float pa = v1a * v3a, pb = v1b * v3b;
                    oa = pa * sigmoidf_(pa);
                    ob = pb * sigmoidf_(pb);
                } else {
                    oa = v1a * sigmoidf_(v1a) * v3a;
                    ob = v1b * sigmoidf_(v1b) * v3b;
                }
                __half2 h2 = __floats2half2_rn(oa, ob);
                *(__half2*)&O[orow * HID + n0 + wn + ni * 8 + ((lane & 3) << 1)] = h2;
            }
        }
}

// ================ down: Y = H @ W2, tile 128(M) x 128(N) =========================
template<bool ROUTED>
__global__ __launch_bounds__(256, 2) void down_k(
        const fp16* __restrict__ H, const float* __restrict__ W2,
        float* __restrict__ out)
{
    int e  = ROUTED ? blockIdx.z : 0;
    int M  = ROUTED ? g_counts[e] : NT;
    int m0 = blockIdx.x * 128;
    if (m0 >= M) return;
    int n0 = blockIdx.y * 128;
    size_t woff = ROUTED ? (size_t)e * HID * DIM : 0;
    const float* w2 = W2 + woff;

    extern __shared__ char smem[];
    int tid = threadIdx.x, lane = tid & 31, warp = tid >> 5;
    int wm = (warp & 1) * 64, wn = (warp >> 1) * 32;

    int ar = tid >> 1, ac = (tid & 1) * 16;
    int gr = m0 + ar; if (gr >= M) gr = m0;
    size_t rid = ROUTED ? (size_t)g_entries[e * NT + gr] : (size_t)gr;
    const fp16* srcA = H + rid * HID + ac;

    int br = tid >> 3, bc = (tid & 7) * 16;
    const float* srcB = w2 + (size_t)br * DIM + n0 + bc;

    uint32_t sb = saddr(smem);
    uint32_t offA = (uint32_t)(ar * APITCH + ac) * 2;
    uint32_t offB = (A_ST + br * BP_DN + bc) * 2;

    float acc[4][4][4] = {};
    float4 bv[4];

    auto loadA = [&](int st, int k0) {
        uint32_t base = sb + st * DOWN_STAGE;
        cpa(base + offA,      srcA + k0);
        cpa(base + offA + 16, srcA + k0 + 8);
    };
    auto ldgB = [&](int k0) {
        const float4* p = (const float4*)(srcB + (size_t)k0 * DIM);
        bv[0] = __ldg(p);     bv[1] = __ldg(p + 1);
        bv[2] = __ldg(p + 2); bv[3] = __ldg(p + 3);
    };
    auto stsB = [&](int st) {
        char* base = smem + st * DOWN_STAGE;
        uint4 o0, o1;
        o0.x = h2u(bv[0].x, bv[0].y); o0.y = h2u(bv[0].z, bv[0].w);
        o0.z = h2u(bv[1].x, bv[1].y); o0.w = h2u(bv[1].z, bv[1].w);
        o1.x = h2u(bv[2].x, bv[2].y); o1.y = h2u(bv[2].z, bv[2].w);
        o1.z = h2u(bv[3].x, bv[3].y); o1.w = h2u(bv[3].z, bv[3].w);
        *(uint4*)(base + offB)      = o0;
        *(uint4*)(base + offB + 16) = o1;
    };

    // prologue
    ldgB(0);  stsB(0);  ldgB(KC);
    loadA(0, 0);      cp_commit();
    loadA(1, KC);     cp_commit();
    loadA(2, 2 * KC); cp_commit();

    const int KT = HID / KC;
    for (int t = 0; t < KT; t++) {
        int st = t & 3;
        cp_wait2();
        __syncthreads();
        if (t + 1 < KT) stsB((t + 1) & 3);
        if (t + 2 < KT) ldgB((t + 2) * KC);
        if (t + 3 < KT) loadA((t + 3) & 3, (t + 3) * KC);
        cp_commit();

        uint32_t base = sb + st * DOWN_STAGE;
        #pragma unroll
        for (int kk = 0; kk < KC; kk += 16) {
            uint32_t ah[4][4];
            #pragma unroll
            for (int mi = 0; mi < 4; mi++) {
                uint32_t ao = ((wm + mi * 16 + (lane & 15)) * APITCH + kk + ((lane >> 4) << 3)) * 2;
                ldsm_x4(ah[mi], base + ao);
            }
            uint32_t bh[2][4];
            #pragma unroll
            for (int g = 0; g < 2; g++) {
                uint32_t bo = ((kk + (lane & 15)) * BP_DN + wn + g * 16 + ((lane >> 4) << 3)) * 2;
                ldsm_x4t(bh[g], base + A_ST * 2 + bo);
            }
            #pragma unroll
            for (int ni = 0; ni < 4; ni++) {
                int g = ni >> 1, o = (ni & 1) * 2;
                #pragma unroll
                for (int mi = 0; mi < 4; mi++)
                    mma16816(acc[mi][ni], ah[mi], &bh[g][o]);
            }
        }
        __syncthreads();
    }

    #pragma unroll
    for (int mi = 0; mi < 4; mi++)
        #pragma unroll
        for (int half = 0; half < 2; half++) {
            int r = m0 + wm + mi * 16 + (lane >> 2) + half * 8;
            if (r >= M) continue;
            if (ROUTED) {
                int slot = g_entries[e * NT + r];
                int tok  = slot >> 2;
                float w  = g_slotw[slot];
                #pragma unroll
                for (int ni = 0; ni < 4; ni++) {
                    int col = n0 + wn + ni * 8 + ((lane & 3) << 1);
                    atomicAdd(&out[(size_t)tok * DIM + col],     acc[mi][ni][half * 2 + 0] * w);
                    atomicAdd(&out[(size_t)tok * DIM + col + 1], acc[mi][ni][half * 2 + 1] * w);
                }
            } else {
                #pragma unroll
                for (int ni = 0; ni < 4; ni++) {
                    float2 o;
                    o.x = acc[mi][ni][half * 2 + 0];
                    o.y = acc[mi][ni][half * 2 + 1];
                    *(float2*)&out[(size_t)r * DIM + n0 + wn + ni * 8 + ((lane & 3) << 1)] = o;
                }
            }
        }
}

static void* sym(const void* s) { void* p; cudaGetSymbolAddress(&p, s); return p; }

extern "C" void kernel_launch(void* const* d_in, const int* in_sizes, int n_in,
                              void* d_out, int out_size)
{
    (void)in_sizes; (void)n_in; (void)out_size;
    const float* x   = (const float*)d_in[0];
    const float* gw  = (const float*)d_in[1];
    const float* gb  = (const float*)d_in[2];
    const float* w1s = (const float*)d_in[3];
    const float* w2s = (const float*)d_in[4];
    const float* w3s = (const float*)d_in[5];
    const float* w1r = (const float*)d_in[6];
    const float* w2r = (const float*)d_in[7];
    const float* w3r = (const float*)d_in[8];
    float* out = (float*)d_out;

    fp16 *x16 = (fp16*)sym(g_x16);
    fp16 *Hs = (fp16*)sym(g_Hs), *Hr = (fp16*)sym(g_Hr);

    cudaFuncSetAttribute(up_k<false>,  cudaFuncAttributeMaxDynamicSharedMemorySize, UP_SMEM);
    cudaFuncSetAttribute(up_k<true>,   cudaFuncAttributeMaxDynamicSharedMemorySize, UP_SMEM);
    cudaFuncSetAttribute(down_k<false>, cudaFuncAttributeMaxDynamicSharedMemorySize, DOWN_SMEM);
    cudaFuncSetAttribute(down_k<true>,  cudaFuncAttributeMaxDynamicSharedMemorySize, DOWN_SMEM);

    zero_counts_kernel<<<1, 32>>>();
    gate_kernel<<<NT, 256>>>(x, gw, gb);

    {
        int n4 = (int)((size_t)NT * DIM / 4);
        cvtx_kernel<<<n4 / (256 * 8), 256>>>((const float4*)x, (uint2*)x16);
    }

    // shared expert
    up_k<false><<<dim3(NT / 128, HID / 64), 256, UP_SMEM>>>(x16, w1s, w3s, Hs);
    down_k<false><<<dim3(NT / 128, DIM / 128), 256, DOWN_SMEM>>>(Hs, w2s, out);

    // routed experts
    up_k<true><<<dim3(NT / 128, HID / 64, NE), 256, UP_SMEM>>>(x16, w1r, w3r, Hr);
    down_k<true><<<dim3(NT / 128, DIM / 128, NE), 256, DOWN_SMEM>>>(Hr, w2r, out);
}